// round 4
// baseline (speedup 1.0000x reference)
#include <cuda_runtime.h>
#include <cstdint>

#define Bq 256
#define Sq 512
#define Eq 256
#define Hq 256
#define G4 1024
#define NB 128
#define MASKVAL -100000.0f
#define TINYF 1.17549435e-38f

// ---------------- device globals (static scratch) ----------------
__device__ float d_emb[(size_t)Sq * Bq * Eq];        // [s][b][e]
__device__ float d_XgEnc[(size_t)Sq * Bq * G4];      // [s][b][j]  emb @ enc_Wih^T (no bias)
__device__ float d_Dg[(size_t)Sq * Bq * G4];         // [s][b][j]  emb @ dec_Wih^T (no bias)
__device__ float d_encout[(size_t)Sq * Bq * Hq];     // [s][b][h]
__device__ float d_refproj[(size_t)Sq * Bq * Hq];    // [s][b][h]
__device__ float d_hbuf[2 * Bq * Hq];                // double-buffered h
__device__ float d_c[Bq * Hq];
__device__ float d_q[Bq * Hq];
__device__ unsigned char d_mask[Bq * Sq];
__device__ int d_chosen[Bq];
__device__ unsigned int d_keys[(Sq - 1) * 2];
__device__ float d_lp[(Sq - 1) * Bq];                // [t][b]
__device__ int d_idx[(Sq - 1) * Bq];                 // [t][b]
__device__ unsigned int g_cnt = 0;
__device__ unsigned int g_gen = 0;

// ---------------- math helpers (XLA f32 semantics) ----------------
__device__ __forceinline__ float xtanh(float x) {
    float ax = fabsf(x);
    float xc = fminf(fmaxf(x, -7.90531110763549805f), 7.90531110763549805f);
    float x2 = xc * xc;
    float p = -2.76076847742355e-16f;
    p = fmaf(p, x2, 2.00018790482477e-13f);
    p = fmaf(p, x2, -8.60467152213735e-11f);
    p = fmaf(p, x2, 5.12229709037114e-08f);
    p = fmaf(p, x2, 1.48572235717979e-05f);
    p = fmaf(p, x2, 6.37261928875436e-04f);
    p = fmaf(p, x2, 4.89352455891786e-03f);
    float q = 1.19825839466702e-06f;
    q = fmaf(q, x2, 1.18534705686654e-04f);
    q = fmaf(q, x2, 2.26843463243900e-03f);
    q = fmaf(q, x2, 4.89352518554385e-03f);
    float t = (xc * p) / q;
    return (ax < 0.0004f) ? x : t;
}

__device__ __forceinline__ float xsigmoid(float x) {
    return 1.0f / (1.0f + expf(-x));
}

__device__ __forceinline__ unsigned int rotl32(unsigned int v, int r) {
    return (v << r) | (v >> (32 - r));
}

__device__ __forceinline__ void threefry2x32(unsigned int k0, unsigned int k1,
                                             unsigned int x0, unsigned int x1,
                                             unsigned int& o0, unsigned int& o1) {
    unsigned int ks2 = k0 ^ k1 ^ 0x1BD11BDAu;
    x0 += k0; x1 += k1;
#define TF_RND(r) { x0 += x1; x1 = rotl32(x1, r); x1 ^= x0; }
    TF_RND(13) TF_RND(15) TF_RND(26) TF_RND(6)
    x0 += k1; x1 += ks2 + 1u;
    TF_RND(17) TF_RND(29) TF_RND(16) TF_RND(24)
    x0 += ks2; x1 += k0 + 2u;
    TF_RND(13) TF_RND(15) TF_RND(26) TF_RND(6)
    x0 += k0; x1 += k1 + 3u;
    TF_RND(17) TF_RND(29) TF_RND(16) TF_RND(24)
    x0 += k1; x1 += ks2 + 4u;
    TF_RND(13) TF_RND(15) TF_RND(26) TF_RND(6)
    x0 += ks2; x1 += k0 + 5u;
#undef TF_RND
    o0 = x0; o1 = x1;
}

// Partitionable-mode 32-bit random bits: counter = 64-bit flat index (hi, lo),
// result = o0 ^ o1.
__device__ __forceinline__ unsigned int tf_bits32(unsigned int k0, unsigned int k1,
                                                  unsigned int idx) {
    unsigned int o0, o1;
    threefry2x32(k0, k1, 0u, idx, o0, o1);
    return o0 ^ o1;
}

__device__ __forceinline__ float gumbel_from_bits(unsigned int bits) {
    float f = __uint_as_float((bits >> 9) | 0x3f800000u) - 1.0f;
    float u = f + TINYF;
    u = fmaxf(TINYF, u);
    return -logf(-logf(u));
}

// ---------------- grid-wide barrier (all NB blocks co-resident) ----------------
__device__ __forceinline__ void gsync(unsigned int& gen) {
    __syncthreads();
    if (threadIdx.x == 0) {
        __threadfence();
        unsigned int t = atomicAdd(&g_cnt, 1u);
        if (t == NB - 1) {
            atomicExch(&g_cnt, 0u);
            __threadfence();
            atomicExch(&g_gen, gen + 1);
        } else {
            while (atomicAdd(&g_gen, 0u) == gen) { }
            __threadfence();
        }
    }
    gen++;
    __syncthreads();
}

// ---------------- fused gates-GEMM + LSTM cell (one step) ----------------
// tiles: 8 (b) x 16 (h) = 128 blocks; block tile = 32 b x 16 h x 4 gates
__device__ __forceinline__ void lstm_phase(
    int bid, int tid,
    const float* __restrict__ hin, float* __restrict__ hout,
    const float* __restrict__ Whh, const float* __restrict__ bih,
    const float* __restrict__ bhh,
    const float* __restrict__ xg,         // encoder: pre-offset [b][j]; decoder: d_Dg base
    const int* __restrict__ gIdx,         // decoder: d_chosen, else null
    float* __restrict__ encout,           // encoder: pre-offset, else null
    float (*As)[32], float (*Bs)[64])
{
    int tb = bid >> 4, th = bid & 15;
    int bm = tb * 32, h0 = th * 16;
    int tx = tid & 15, ty = tid >> 4;
    float acc[2][4];
#pragma unroll
    for (int i = 0; i < 2; i++)
#pragma unroll
        for (int g = 0; g < 4; g++) acc[i][g] = 0.0f;

    for (int k0 = 0; k0 < Hq; k0 += 16) {
#pragma unroll
        for (int l = 0; l < 2; l++) {
            int idx = tid + l * 256;
            int m = idx >> 4, kk = idx & 15;
            As[kk][m] = hin[(bm + m) * Hq + k0 + kk];
        }
#pragma unroll
        for (int l = 0; l < 4; l++) {
            int idx = tid + l * 256;
            int c = idx >> 4, kk = idx & 15;
            int g = c >> 4, hh = c & 15;
            Bs[kk][c] = Whh[(g * Hq + h0 + hh) * Hq + k0 + kk];
        }
        __syncthreads();
#pragma unroll
        for (int kk = 0; kk < 16; kk++) {
            float2 a2 = *reinterpret_cast<const float2*>(&As[kk][ty * 2]);
            float b0 = Bs[kk][tx], b1 = Bs[kk][16 + tx];
            float b2 = Bs[kk][32 + tx], b3 = Bs[kk][48 + tx];
            acc[0][0] = fmaf(a2.x, b0, acc[0][0]);
            acc[0][1] = fmaf(a2.x, b1, acc[0][1]);
            acc[0][2] = fmaf(a2.x, b2, acc[0][2]);
            acc[0][3] = fmaf(a2.x, b3, acc[0][3]);
            acc[1][0] = fmaf(a2.y, b0, acc[1][0]);
            acc[1][1] = fmaf(a2.y, b1, acc[1][1]);
            acc[1][2] = fmaf(a2.y, b2, acc[1][2]);
            acc[1][3] = fmaf(a2.y, b3, acc[1][3]);
        }
        __syncthreads();
    }

    int h = h0 + tx;
#pragma unroll
    for (int i = 0; i < 2; i++) {
        int b = bm + ty * 2 + i;
        size_t xrow;
        if (gIdx) xrow = ((size_t)gIdx[b] * Bq + b) * G4;
        else      xrow = (size_t)b * G4;
        float gi = acc[i][0] + xg[xrow + h]            + bih[h]            + bhh[h];
        float gf = acc[i][1] + xg[xrow + Hq + h]       + bih[Hq + h]       + bhh[Hq + h];
        float gg = acc[i][2] + xg[xrow + 2 * Hq + h]   + bih[2 * Hq + h]   + bhh[2 * Hq + h];
        float go = acc[i][3] + xg[xrow + 3 * Hq + h]   + bih[3 * Hq + h]   + bhh[3 * Hq + h];
        int idx = b * Hq + h;
        float cc = d_c[idx];
        float cn = xsigmoid(gf) * cc + xsigmoid(gi) * xtanh(gg);
        float hn = xsigmoid(go) * xtanh(cn);
        d_c[idx] = cn;
        hout[idx] = hn;
        if (encout) encout[idx] = hn;
    }
}

// ---------------- persistent encoder ----------------
__global__ __launch_bounds__(256, 1) void k_encoder(const float* __restrict__ Whh,
                                                    const float* __restrict__ bih,
                                                    const float* __restrict__ bhh) {
    __shared__ float As[16][32];
    __shared__ float Bs[16][64];
    __shared__ unsigned int s_gen0;
    int tid = threadIdx.x, bid = blockIdx.x;
    if (tid == 0) s_gen0 = atomicAdd(&g_gen, 0u);
    __syncthreads();
    unsigned int gen = s_gen0;

    for (int s = 0; s < Sq; s++) {
        const float* hin = d_hbuf + (s & 1) * (Bq * Hq);
        float* hout = d_hbuf + ((s & 1) ^ 1) * (Bq * Hq);
        lstm_phase(bid, tid, hin, hout, Whh, bih, bhh,
                   d_XgEnc + (size_t)s * Bq * G4, nullptr,
                   d_encout + (size_t)s * Bq * Hq, As, Bs);
        gsync(gen);
    }
}

// ---------------- persistent decoder ----------------
__global__ __launch_bounds__(256, 1) void k_decoder(const float* __restrict__ Whh,
                                                    const float* __restrict__ bih,
                                                    const float* __restrict__ bhh,
                                                    const float* __restrict__ Wq,
                                                    const float* __restrict__ vvec) {
    __shared__ float As[16][32];
    __shared__ float Bs[16][64];
    __shared__ float qs[Hq];
    __shared__ float vsm[Hq];
    __shared__ float ls[Sq];
    __shared__ float rv[256];
    __shared__ int   ri[256];
    __shared__ float sv[256];
    __shared__ unsigned int s_gen0;

    int tid = threadIdx.x, bid = blockIdx.x;
    if (tid == 0) s_gen0 = atomicAdd(&g_gen, 0u);
    vsm[tid] = vvec[tid];
    __syncthreads();
    unsigned int gen = s_gen0;

    int tb = bid >> 4, th = bid & 15;
    int bm = tb * 32, h0 = th * 16;
    int tx = tid & 15, ty = tid >> 4;
    int w = tid >> 5, lane = tid & 31;

    for (int t = 0; t < Sq - 1; t++) {
        const float* hin = d_hbuf + (t & 1) * (Bq * Hq);
        float* hout = d_hbuf + ((t & 1) ^ 1) * (Bq * Hq);

        // Phase A: gates GEMM + cell (fused)
        lstm_phase(bid, tid, hin, hout, Whh, bih, bhh, d_Dg, d_chosen, nullptr, As, Bs);
        gsync(gen);

        // Phase B: q = h_new @ Wq^T ; block tile 32 b x 16 h
        {
            float acc0 = 0.0f, acc1 = 0.0f;
            for (int k0 = 0; k0 < Hq; k0 += 16) {
#pragma unroll
                for (int l = 0; l < 2; l++) {
                    int idx = tid + l * 256;
                    int m = idx >> 4, kk = idx & 15;
                    As[kk][m] = hout[(bm + m) * Hq + k0 + kk];
                }
                {
                    int hh = tid >> 4, kk = tid & 15;
                    Bs[kk][hh] = Wq[(h0 + hh) * Hq + k0 + kk];
                }
                __syncthreads();
#pragma unroll
                for (int kk = 0; kk < 16; kk++) {
                    float2 a2 = *reinterpret_cast<const float2*>(&As[kk][ty * 2]);
                    float bq = Bs[kk][tx];
                    acc0 = fmaf(a2.x, bq, acc0);
                    acc1 = fmaf(a2.y, bq, acc1);
                }
                __syncthreads();
            }
            d_q[(bm + ty * 2) * Hq + h0 + tx] = acc0;
            d_q[(bm + ty * 2 + 1) * Hq + h0 + tx] = acc1;
        }
        gsync(gen);

        // Phase C: attention logits + gumbel argmax + log-softmax (2 b per block)
        {
            unsigned int kk0 = d_keys[2 * t], kk1 = d_keys[2 * t + 1];
            for (int rep = 0; rep < 2; rep++) {
                int b = bid * 2 + rep;
                qs[tid] = d_q[b * Hq + tid];
                __syncthreads();
                const float4* qs4 = reinterpret_cast<const float4*>(qs);
                const float4* vs4 = reinterpret_cast<const float4*>(vsm);
                float4 q0 = qs4[lane], q1 = qs4[lane + 32];
                float4 v0 = vs4[lane], v1 = vs4[lane + 32];
                for (int it = 0; it < 64; it++) {
                    int s = it * 8 + w;
                    const float4* rp4 = reinterpret_cast<const float4*>(
                        d_refproj + ((size_t)s * Bq + b) * Hq);
                    float4 r0 = rp4[lane];
                    float4 r1 = rp4[lane + 32];
                    float sum = 0.0f;
                    sum = fmaf(v0.x, xtanh(q0.x + r0.x), sum);
                    sum = fmaf(v0.y, xtanh(q0.y + r0.y), sum);
                    sum = fmaf(v0.z, xtanh(q0.z + r0.z), sum);
                    sum = fmaf(v0.w, xtanh(q0.w + r0.w), sum);
                    sum = fmaf(v1.x, xtanh(q1.x + r1.x), sum);
                    sum = fmaf(v1.y, xtanh(q1.y + r1.y), sum);
                    sum = fmaf(v1.z, xtanh(q1.z + r1.z), sum);
                    sum = fmaf(v1.w, xtanh(q1.w + r1.w), sum);
#pragma unroll
                    for (int off = 16; off > 0; off >>= 1)
                        sum += __shfl_down_sync(0xffffffffu, sum, off);
                    if (lane == 0) ls[s] = sum;
                }
                __syncthreads();

                // mask + gumbel, per-thread 2 positions (partitionable bits)
                float out2[2];
#pragma unroll
                for (int u = 0; u < 2; u++) {
                    int s = tid + (u << 8);
                    float logit = d_mask[(size_t)b * Sq + s] ? MASKVAL : ls[s];
                    ls[s] = logit;
                    unsigned int i = (unsigned int)(b * Sq + s);
                    out2[u] = logit + gumbel_from_bits(tf_bits32(kk0, kk1, i));
                }
                __syncthreads();

                // argmax (tie -> smaller index)
                float bv; int bi;
                if (out2[0] >= out2[1]) { bv = out2[0]; bi = tid; }
                else { bv = out2[1]; bi = tid + 256; }
                rv[tid] = bv; ri[tid] = bi;
                __syncthreads();
                for (int off = 128; off > 0; off >>= 1) {
                    if (tid < off) {
                        float v2 = rv[tid + off]; int i2 = ri[tid + off];
                        if (v2 > rv[tid] || (v2 == rv[tid] && i2 < ri[tid])) {
                            rv[tid] = v2; ri[tid] = i2;
                        }
                    }
                    __syncthreads();
                }
                int ch = ri[0];
                __syncthreads();

                // log-softmax of masked logits
                rv[tid] = fmaxf(ls[tid], ls[tid + 256]);
                __syncthreads();
                for (int off = 128; off > 0; off >>= 1) {
                    if (tid < off) rv[tid] = fmaxf(rv[tid], rv[tid + off]);
                    __syncthreads();
                }
                float m = rv[0];
                sv[tid] = expf(ls[tid] - m) + expf(ls[tid + 256] - m);
                __syncthreads();
                for (int off = 128; off > 0; off >>= 1) {
                    if (tid < off) sv[tid] += sv[tid + off];
                    __syncthreads();
                }
                if (tid == 0) {
                    float lp = (ls[ch] - m) - logf(sv[0]);
                    d_lp[(size_t)t * Bq + b] = lp;
                    d_idx[(size_t)t * Bq + b] = ch;
                    d_chosen[b] = ch;
                    d_mask[(size_t)b * Sq + ch] = 1;
                }
                __syncthreads();
            }
        }
        gsync(gen);
    }
}

// ---------------- init (+ threefry keys, partitionable split) ----------------
__global__ __launch_bounds__(256) void k_init() {
    int i = blockIdx.x * 256 + threadIdx.x;   // 131072 threads
    if (i < 2 * Bq * Hq) d_hbuf[i] = 0.0f;
    if (i < Bq * Hq) d_c[i] = 0.0f;
    if (i < Bq * Sq) d_mask[i] = ((i & (Sq - 1)) == 0) ? 1 : 0;
    if (i < Bq) d_chosen[i] = 0;
    if (i < (Sq - 1)) {
        // partitionable split: key_t = threefry(base_key, (hi=0, lo=t)), both words
        unsigned int o0, o1;
        threefry2x32(0u, 1u, 0u, (unsigned int)i, o0, o1);
        d_keys[2 * i] = o0;
        d_keys[2 * i + 1] = o1;
    }
}

__global__ __launch_bounds__(256) void k_embed(const float* __restrict__ inputs,
                                               const float* __restrict__ W_embed) {
    int i = blockIdx.x * 256 + threadIdx.x;   // S*B*E
    int e = i & (Eq - 1);
    int b = (i >> 8) & (Bq - 1);
    int s = i >> 16;
    const float* inp = inputs + ((size_t)b * Sq + s) * 2;
    d_emb[i] = fmaf(inp[1], W_embed[Eq + e], inp[0] * W_embed[e]);
}

// ---------------- big tiled GEMM: C[M][N] = A[M][K] * W[N][K]^T ----------------
#define BM 64
#define BN 64
#define BK 16
__global__ __launch_bounds__(256) void k_gemm(const float* __restrict__ A,
                                              const float* __restrict__ W,
                                              float* __restrict__ C,
                                              int M, int N, int K) {
    __shared__ float As[BK][BM];
    __shared__ float Bs[BK][BN];
    int bm = blockIdx.y * BM, bn = blockIdx.x * BN;
    int tid = threadIdx.x;
    int tx = tid & 15, ty = tid >> 4;
    float acc[4][4];
#pragma unroll
    for (int i = 0; i < 4; i++)
#pragma unroll
        for (int j = 0; j < 4; j++) acc[i][j] = 0.0f;

    for (int k0 = 0; k0 < K; k0 += BK) {
#pragma unroll
        for (int l = 0; l < 4; l++) {
            int idx = tid + l * 256;
            int m = idx >> 4, kk = idx & 15;
            As[kk][m] = A[(size_t)(bm + m) * K + k0 + kk];
        }
#pragma unroll
        for (int l = 0; l < 4; l++) {
            int idx = tid + l * 256;
            int n = idx >> 4, kk = idx & 15;
            Bs[kk][n] = W[(size_t)(bn + n) * K + k0 + kk];
        }
        __syncthreads();
#pragma unroll
        for (int kk = 0; kk < BK; kk++) {
            float4 a4 = *reinterpret_cast<const float4*>(&As[kk][ty * 4]);
            float4 b4 = *reinterpret_cast<const float4*>(&Bs[kk][tx * 4]);
            float a[4] = {a4.x, a4.y, a4.z, a4.w};
            float b[4] = {b4.x, b4.y, b4.z, b4.w};
#pragma unroll
            for (int i = 0; i < 4; i++)
#pragma unroll
                for (int j = 0; j < 4; j++)
                    acc[i][j] = fmaf(a[i], b[j], acc[i][j]);
        }
        __syncthreads();
    }
#pragma unroll
    for (int i = 0; i < 4; i++) {
        int m = bm + ty * 4 + i;
#pragma unroll
        for (int j = 0; j < 4; j++) {
            int n = bn + tx * 4 + j;
            C[(size_t)m * N + n] = acc[i][j];
        }
    }
}

__global__ __launch_bounds__(256) void k_final(float* __restrict__ out) {
    int i = blockIdx.x * 256 + threadIdx.x;
    const int NLP = Bq * (Sq - 1);
    if (i < NLP) {
        int b = i / (Sq - 1), t = i % (Sq - 1);
        out[i] = d_lp[(size_t)t * Bq + b];
    } else if (i < NLP + Bq * Sq) {
        int j = i - NLP;
        int b = j >> 9, s = j & (Sq - 1);
        out[i] = (s == 0) ? 0.0f : (float)d_idx[(size_t)(s - 1) * Bq + b];
    }
}

// ---------------- host ----------------
extern "C" void kernel_launch(void* const* d_in, const int* in_sizes, int n_in,
                              void* d_out, int out_size) {
    const float* inputs   = (const float*)d_in[0];
    const float* W_embed  = (const float*)d_in[1];
    const float* enc_Wih  = (const float*)d_in[2];
    const float* enc_Whh  = (const float*)d_in[3];
    const float* enc_bih  = (const float*)d_in[4];
    const float* enc_bhh  = (const float*)d_in[5];
    const float* dec_Wih  = (const float*)d_in[6];
    const float* dec_Whh  = (const float*)d_in[7];
    const float* dec_bih  = (const float*)d_in[8];
    const float* dec_bhh  = (const float*)d_in[9];
    const float* Wq       = (const float*)d_in[10];
    const float* Wref     = (const float*)d_in[11];
    const float* v        = (const float*)d_in[12];

    float *p_emb, *p_Xg, *p_Dg, *p_enc, *p_rp;
    cudaGetSymbolAddress((void**)&p_emb, d_emb);
    cudaGetSymbolAddress((void**)&p_Xg, d_XgEnc);
    cudaGetSymbolAddress((void**)&p_Dg, d_Dg);
    cudaGetSymbolAddress((void**)&p_enc, d_encout);
    cudaGetSymbolAddress((void**)&p_rp, d_refproj);

    k_init<<<512, 256>>>();
    k_embed<<<(Sq * Bq * Eq) / 256, 256>>>(inputs, W_embed);

    const int Mbig = Sq * Bq;  // 131072
    {
        dim3 grid(G4 / BN, Mbig / BM);
        k_gemm<<<grid, 256>>>(p_emb, enc_Wih, p_Xg, Mbig, G4, Eq);
    }
    {
        dim3 grid(G4 / BN, Mbig / BM);
        k_gemm<<<grid, 256>>>(p_emb, dec_Wih, p_Dg, Mbig, G4, Eq);
    }

    k_encoder<<<NB, 256>>>(enc_Whh, enc_bih, enc_bhh);

    {
        dim3 grid(Hq / BN, Mbig / BM);
        k_gemm<<<grid, 256>>>(p_enc, Wref, p_rp, Mbig, Hq, Hq);
    }

    k_decoder<<<NB, 256>>>(dec_Whh, dec_bih, dec_bhh, Wq, v);

    k_final<<<(Bq * (Sq - 1) + Bq * Sq + 255) / 256, 256>>>((float*)d_out);
}

// round 5
// speedup vs baseline: 2.3390x; 2.3390x over previous
#include <cuda_runtime.h>
#include <cstdint>

#define Bq 256
#define Sq 512
#define Eq 256
#define Hq 256
#define G4 1024
#define NB_ENC 128
#define NB_DEC 256
#define MASKVAL -100000.0f
#define TINYF 1.17549435e-38f

// ---------------- device globals (static scratch) ----------------
__device__ float d_emb[(size_t)Sq * Bq * Eq];        // [s][b][e]
__device__ float d_XgEnc[(size_t)Sq * Bq * G4];      // [s][b][j]
__device__ float d_Dg[(size_t)Sq * Bq * G4];         // [s][b][j]
__device__ float d_encout[(size_t)Sq * Bq * Hq];     // [s][b][h]
__device__ float d_refproj[(size_t)Bq * Sq * Hq];    // [b][s][h]  (transposed layout!)
__device__ float d_hbuf[2 * Bq * Hq];
__device__ float d_c[Bq * Hq];
__device__ float d_q[Bq * Hq];
__device__ unsigned char d_mask[Bq * Sq];
__device__ int d_chosen[Bq];
__device__ unsigned int d_keys[(Sq - 1) * 2];
__device__ float d_lp[(Sq - 1) * Bq];
__device__ int d_idx[(Sq - 1) * Bq];
__device__ unsigned int g_cnt = 0;
__device__ unsigned int g_gen = 0;

// ---------------- math helpers (XLA f32 semantics) ----------------
__device__ __forceinline__ float xtanh(float x) {
    float ax = fabsf(x);
    float xc = fminf(fmaxf(x, -7.90531110763549805f), 7.90531110763549805f);
    float x2 = xc * xc;
    float p = -2.76076847742355e-16f;
    p = fmaf(p, x2, 2.00018790482477e-13f);
    p = fmaf(p, x2, -8.60467152213735e-11f);
    p = fmaf(p, x2, 5.12229709037114e-08f);
    p = fmaf(p, x2, 1.48572235717979e-05f);
    p = fmaf(p, x2, 6.37261928875436e-04f);
    p = fmaf(p, x2, 4.89352455891786e-03f);
    float q = 1.19825839466702e-06f;
    q = fmaf(q, x2, 1.18534705686654e-04f);
    q = fmaf(q, x2, 2.26843463243900e-03f);
    q = fmaf(q, x2, 4.89352518554385e-03f);
    float t = (xc * p) / q;
    return (ax < 0.0004f) ? x : t;
}

__device__ __forceinline__ float xsigmoid(float x) {
    return 1.0f / (1.0f + expf(-x));
}

__device__ __forceinline__ unsigned int rotl32(unsigned int v, int r) {
    return (v << r) | (v >> (32 - r));
}

__device__ __forceinline__ void threefry2x32(unsigned int k0, unsigned int k1,
                                             unsigned int x0, unsigned int x1,
                                             unsigned int& o0, unsigned int& o1) {
    unsigned int ks2 = k0 ^ k1 ^ 0x1BD11BDAu;
    x0 += k0; x1 += k1;
#define TF_RND(r) { x0 += x1; x1 = rotl32(x1, r); x1 ^= x0; }
    TF_RND(13) TF_RND(15) TF_RND(26) TF_RND(6)
    x0 += k1; x1 += ks2 + 1u;
    TF_RND(17) TF_RND(29) TF_RND(16) TF_RND(24)
    x0 += ks2; x1 += k0 + 2u;
    TF_RND(13) TF_RND(15) TF_RND(26) TF_RND(6)
    x0 += k0; x1 += k1 + 3u;
    TF_RND(17) TF_RND(29) TF_RND(16) TF_RND(24)
    x0 += k1; x1 += ks2 + 4u;
    TF_RND(13) TF_RND(15) TF_RND(26) TF_RND(6)
    x0 += ks2; x1 += k0 + 5u;
#undef TF_RND
    o0 = x0; o1 = x1;
}

__device__ __forceinline__ unsigned int tf_bits32(unsigned int k0, unsigned int k1,
                                                  unsigned int idx) {
    unsigned int o0, o1;
    threefry2x32(k0, k1, 0u, idx, o0, o1);
    return o0 ^ o1;
}

__device__ __forceinline__ float gumbel_from_bits(unsigned int bits) {
    float f = __uint_as_float((bits >> 9) | 0x3f800000u) - 1.0f;
    float u = f + TINYF;
    u = fmaxf(TINYF, u);
    return -logf(-logf(u));
}

// ---------------- grid-wide barrier ----------------
template <int NBLK>
__device__ __forceinline__ void gsync(unsigned int& gen) {
    __syncthreads();
    if (threadIdx.x == 0) {
        __threadfence();
        unsigned int t = atomicAdd(&g_cnt, 1u);
        if (t == NBLK - 1) {
            atomicExch(&g_cnt, 0u);
            __threadfence();
            atomicExch(&g_gen, gen + 1);
        } else {
            while (atomicAdd(&g_gen, 0u) == gen) { }
            __threadfence();
        }
    }
    gen++;
    __syncthreads();
}

// ---------------- fused gates-GEMM + LSTM cell (one step) ----------------
// 128 working blocks: 8 (b) x 16 (h); block tile = 32 b x 16 h x 4 gates.
// Bs columns interleaved c = h*4 + g so the b-operand is one LDS.128.
__device__ __forceinline__ void lstm_phase(
    int bid, int tid,
    const float* __restrict__ hin, float* __restrict__ hout,
    const float* __restrict__ Whh, const float* __restrict__ bih,
    const float* __restrict__ bhh,
    const float* __restrict__ xg,
    const int* __restrict__ gIdx,
    float* __restrict__ encout,
    float (*As)[34], float (*Bs)[68])
{
    int tb = bid >> 4, th = bid & 15;
    int bm = tb * 32, h0 = th * 16;
    int tx = tid & 15, ty = tid >> 4;
    float acc[2][4];
#pragma unroll
    for (int i = 0; i < 2; i++)
#pragma unroll
        for (int g = 0; g < 4; g++) acc[i][g] = 0.0f;

    for (int k0 = 0; k0 < Hq; k0 += 16) {
#pragma unroll
        for (int l = 0; l < 2; l++) {
            int idx = tid + l * 256;
            int m = idx >> 4, kk = idx & 15;
            As[kk][m] = hin[(bm + m) * Hq + k0 + kk];
        }
#pragma unroll
        for (int l = 0; l < 4; l++) {
            int idx = tid + l * 256;
            int c = idx >> 4, kk = idx & 15;
            int h = c >> 2, g = c & 3;
            Bs[kk][c] = Whh[(g * Hq + h0 + h) * Hq + k0 + kk];
        }
        __syncthreads();
#pragma unroll
        for (int kk = 0; kk < 16; kk++) {
            float2 a2 = *reinterpret_cast<const float2*>(&As[kk][ty * 2]);
            float4 b4 = *reinterpret_cast<const float4*>(&Bs[kk][tx * 4]);
            acc[0][0] = fmaf(a2.x, b4.x, acc[0][0]);
            acc[0][1] = fmaf(a2.x, b4.y, acc[0][1]);
            acc[0][2] = fmaf(a2.x, b4.z, acc[0][2]);
            acc[0][3] = fmaf(a2.x, b4.w, acc[0][3]);
            acc[1][0] = fmaf(a2.y, b4.x, acc[1][0]);
            acc[1][1] = fmaf(a2.y, b4.y, acc[1][1]);
            acc[1][2] = fmaf(a2.y, b4.z, acc[1][2]);
            acc[1][3] = fmaf(a2.y, b4.w, acc[1][3]);
        }
        __syncthreads();
    }

    int h = h0 + tx;
#pragma unroll
    for (int i = 0; i < 2; i++) {
        int b = bm + ty * 2 + i;
        size_t xrow;
        if (gIdx) xrow = ((size_t)gIdx[b] * Bq + b) * G4;
        else      xrow = (size_t)b * G4;
        float gi = acc[i][0] + xg[xrow + h]          + bih[h]          + bhh[h];
        float gf = acc[i][1] + xg[xrow + Hq + h]     + bih[Hq + h]     + bhh[Hq + h];
        float gg = acc[i][2] + xg[xrow + 2*Hq + h]   + bih[2*Hq + h]   + bhh[2*Hq + h];
        float go = acc[i][3] + xg[xrow + 3*Hq + h]   + bih[3*Hq + h]   + bhh[3*Hq + h];
        int idx = b * Hq + h;
        float cc = d_c[idx];
        float cn = xsigmoid(gf) * cc + xsigmoid(gi) * xtanh(gg);
        float hn = xsigmoid(go) * xtanh(cn);
        d_c[idx] = cn;
        hout[idx] = hn;
        if (encout) encout[idx] = hn;
    }
}

// ---------------- persistent encoder (128 blocks) ----------------
__global__ __launch_bounds__(256, 1) void k_encoder(const float* __restrict__ Whh,
                                                    const float* __restrict__ bih,
                                                    const float* __restrict__ bhh) {
    __shared__ float As[16][34];
    __shared__ float Bs[16][68];
    __shared__ unsigned int s_gen0;
    int tid = threadIdx.x, bid = blockIdx.x;
    if (tid == 0) s_gen0 = atomicAdd(&g_gen, 0u);
    __syncthreads();
    unsigned int gen = s_gen0;

    for (int s = 0; s < Sq; s++) {
        const float* hin = d_hbuf + (s & 1) * (Bq * Hq);
        float* hout = d_hbuf + ((s & 1) ^ 1) * (Bq * Hq);
        lstm_phase(bid, tid, hin, hout, Whh, bih, bhh,
                   d_XgEnc + (size_t)s * Bq * G4, nullptr,
                   d_encout + (size_t)s * Bq * Hq, As, Bs);
        gsync<NB_ENC>(gen);
    }
}

// ---------------- persistent decoder (256 blocks, 2 CTA/SM) ----------------
__global__ __launch_bounds__(256, 2) void k_decoder(const float* __restrict__ Whh,
                                                    const float* __restrict__ bih,
                                                    const float* __restrict__ bhh,
                                                    const float* __restrict__ Wq,
                                                    const float* __restrict__ vvec) {
    __shared__ float As[16][34];
    __shared__ float Bs[16][68];
    __shared__ float qs[Hq];
    __shared__ float vsm[Hq];
    __shared__ float ls[Sq];
    __shared__ float rv[256];
    __shared__ int   ri[256];
    __shared__ float sv[256];
    __shared__ unsigned int s_gen0;

    int tid = threadIdx.x, bid = blockIdx.x;
    if (tid == 0) s_gen0 = atomicAdd(&g_gen, 0u);
    vsm[tid] = vvec[tid];
    __syncthreads();
    unsigned int gen = s_gen0;

    int tb = bid >> 4, th = bid & 15;
    int bm = tb * 32, h0 = th * 16;
    int tx = tid & 15, ty = tid >> 4;
    int w = tid >> 5, lane = tid & 31;
    int b = bid;  // phase C batch row

    for (int t = 0; t < Sq - 1; t++) {
        const float* hin = d_hbuf + (t & 1) * (Bq * Hq);
        float* hout = d_hbuf + ((t & 1) ^ 1) * (Bq * Hq);

        // Phase A: gates GEMM + cell (blocks 0..127)
        if (bid < 128)
            lstm_phase(bid, tid, hin, hout, Whh, bih, bhh, d_Dg, d_chosen, nullptr, As, Bs);
        gsync<NB_DEC>(gen);

        // Phase B: q = h_new @ Wq^T (blocks 0..127; tile 32 b x 16 h)
        if (bid < 128) {
            float acc0 = 0.0f, acc1 = 0.0f;
            for (int k0 = 0; k0 < Hq; k0 += 16) {
#pragma unroll
                for (int l = 0; l < 2; l++) {
                    int idx = tid + l * 256;
                    int m = idx >> 4, kk = idx & 15;
                    As[kk][m] = hout[(bm + m) * Hq + k0 + kk];
                }
                {
                    int hh = tid >> 4, kk = tid & 15;
                    Bs[kk][hh] = Wq[(h0 + hh) * Hq + k0 + kk];
                }
                __syncthreads();
#pragma unroll
                for (int kk = 0; kk < 16; kk++) {
                    float2 a2 = *reinterpret_cast<const float2*>(&As[kk][ty * 2]);
                    float bq = Bs[kk][tx];
                    acc0 = fmaf(a2.x, bq, acc0);
                    acc1 = fmaf(a2.y, bq, acc1);
                }
                __syncthreads();
            }
            d_q[(bm + ty * 2) * Hq + h0 + tx] = acc0;
            d_q[(bm + ty * 2 + 1) * Hq + h0 + tx] = acc1;
        }
        gsync<NB_DEC>(gen);

        // Phase C: attention logits + gumbel argmax + log-softmax (1 b per block)
        {
            unsigned int kk0 = d_keys[2 * t], kk1 = d_keys[2 * t + 1];
            qs[tid] = d_q[b * Hq + tid];
            __syncthreads();
            const float4* qs4 = reinterpret_cast<const float4*>(qs);
            const float4* vs4 = reinterpret_cast<const float4*>(vsm);
            float4 q0 = qs4[lane], q1 = qs4[lane + 32];
            float4 v0 = vs4[lane], v1 = vs4[lane + 32];
            const unsigned char* mrow = d_mask + (size_t)b * Sq;
            const float* rbase = d_refproj + (size_t)b * Sq * Hq;

            for (int it = 0; it < 32; it++) {
                int s0 = it * 16 + w;
                int s1 = s0 + 8;
                bool m0 = mrow[s0] != 0;
                bool m1 = mrow[s1] != 0;
                const float4* p0 = reinterpret_cast<const float4*>(rbase + (size_t)s0 * Hq);
                const float4* p1 = reinterpret_cast<const float4*>(rbase + (size_t)s1 * Hq);
                float4 r0a, r0b, r1a, r1b;
                if (!m0) { r0a = p0[lane]; r0b = p0[lane + 32]; }
                if (!m1) { r1a = p1[lane]; r1b = p1[lane + 32]; }
                float sum0 = 0.0f, sum1 = 0.0f;
                if (!m0) {
                    sum0 = fmaf(v0.x, xtanh(q0.x + r0a.x), sum0);
                    sum0 = fmaf(v0.y, xtanh(q0.y + r0a.y), sum0);
                    sum0 = fmaf(v0.z, xtanh(q0.z + r0a.z), sum0);
                    sum0 = fmaf(v0.w, xtanh(q0.w + r0a.w), sum0);
                    sum0 = fmaf(v1.x, xtanh(q1.x + r0b.x), sum0);
                    sum0 = fmaf(v1.y, xtanh(q1.y + r0b.y), sum0);
                    sum0 = fmaf(v1.z, xtanh(q1.z + r0b.z), sum0);
                    sum0 = fmaf(v1.w, xtanh(q1.w + r0b.w), sum0);
                }
                if (!m1) {
                    sum1 = fmaf(v0.x, xtanh(q0.x + r1a.x), sum1);
                    sum1 = fmaf(v0.y, xtanh(q0.y + r1a.y), sum1);
                    sum1 = fmaf(v0.z, xtanh(q0.z + r1a.z), sum1);
                    sum1 = fmaf(v0.w, xtanh(q0.w + r1a.w), sum1);
                    sum1 = fmaf(v1.x, xtanh(q1.x + r1b.x), sum1);
                    sum1 = fmaf(v1.y, xtanh(q1.y + r1b.y), sum1);
                    sum1 = fmaf(v1.z, xtanh(q1.z + r1b.z), sum1);
                    sum1 = fmaf(v1.w, xtanh(q1.w + r1b.w), sum1);
                }
#pragma unroll
                for (int off = 16; off > 0; off >>= 1) {
                    sum0 += __shfl_down_sync(0xffffffffu, sum0, off);
                    sum1 += __shfl_down_sync(0xffffffffu, sum1, off);
                }
                if (lane == 0) {
                    ls[s0] = m0 ? MASKVAL : sum0;
                    ls[s1] = m1 ? MASKVAL : sum1;
                }
            }
            __syncthreads();

            // gumbel for unmasked positions only (masked can never win; gumbel >= -4.47)
            float out2[2];
#pragma unroll
            for (int u = 0; u < 2; u++) {
                int s = tid + (u << 8);
                float logit = ls[s];
                if (logit == MASKVAL) out2[u] = -1e30f;
                else out2[u] = logit + gumbel_from_bits(
                                   tf_bits32(kk0, kk1, (unsigned int)(b * Sq + s)));
            }
            __syncthreads();

            // argmax (tie -> smaller index)
            float bv; int bi;
            if (out2[0] >= out2[1]) { bv = out2[0]; bi = tid; }
            else { bv = out2[1]; bi = tid + 256; }
            rv[tid] = bv; ri[tid] = bi;
            __syncthreads();
            for (int off = 128; off > 0; off >>= 1) {
                if (tid < off) {
                    float v2 = rv[tid + off]; int i2 = ri[tid + off];
                    if (v2 > rv[tid] || (v2 == rv[tid] && i2 < ri[tid])) {
                        rv[tid] = v2; ri[tid] = i2;
                    }
                }
                __syncthreads();
            }
            int ch = ri[0];
            __syncthreads();

            // log-softmax of masked logits
            rv[tid] = fmaxf(ls[tid], ls[tid + 256]);
            __syncthreads();
            for (int off = 128; off > 0; off >>= 1) {
                if (tid < off) rv[tid] = fmaxf(rv[tid], rv[tid + off]);
                __syncthreads();
            }
            float m = rv[0];
            sv[tid] = expf(ls[tid] - m) + expf(ls[tid + 256] - m);
            __syncthreads();
            for (int off = 128; off > 0; off >>= 1) {
                if (tid < off) sv[tid] += sv[tid + off];
                __syncthreads();
            }
            if (tid == 0) {
                float lp = (ls[ch] - m) - logf(sv[0]);
                d_lp[(size_t)t * Bq + b] = lp;
                d_idx[(size_t)t * Bq + b] = ch;
                d_chosen[b] = ch;
                d_mask[(size_t)b * Sq + ch] = 1;
            }
            __syncthreads();
        }
        gsync<NB_DEC>(gen);
    }
}

// ---------------- init (+ threefry keys, partitionable split) ----------------
__global__ __launch_bounds__(256) void k_init() {
    int i = blockIdx.x * 256 + threadIdx.x;
    if (i < 2 * Bq * Hq) d_hbuf[i] = 0.0f;
    if (i < Bq * Hq) d_c[i] = 0.0f;
    if (i < Bq * Sq) d_mask[i] = ((i & (Sq - 1)) == 0) ? 1 : 0;
    if (i < Bq) d_chosen[i] = 0;
    if (i < (Sq - 1)) {
        unsigned int o0, o1;
        threefry2x32(0u, 1u, 0u, (unsigned int)i, o0, o1);
        d_keys[2 * i] = o0;
        d_keys[2 * i + 1] = o1;
    }
}

__global__ __launch_bounds__(256) void k_embed(const float* __restrict__ inputs,
                                               const float* __restrict__ W_embed) {
    int i = blockIdx.x * 256 + threadIdx.x;
    int e = i & (Eq - 1);
    int b = (i >> 8) & (Bq - 1);
    int s = i >> 16;
    const float* inp = inputs + ((size_t)b * Sq + s) * 2;
    d_emb[i] = fmaf(inp[1], W_embed[Eq + e], inp[0] * W_embed[e]);
}

// ---------------- big tiled GEMM: C = A[M][K] * W[N][K]^T ; 128x128x16, 8x8 ----------------
__global__ __launch_bounds__(256) void k_gemm2(const float* __restrict__ A,
                                               const float* __restrict__ W,
                                               float* __restrict__ C,
                                               int M, int N, int K, int transOut) {
    __shared__ float As[16][136];
    __shared__ float Bs[16][136];
    int bm = blockIdx.y * 128, bn = blockIdx.x * 128;
    int tid = threadIdx.x;
    int tx = tid & 15, ty = tid >> 4;
    float acc[8][8];
#pragma unroll
    for (int i = 0; i < 8; i++)
#pragma unroll
        for (int j = 0; j < 8; j++) acc[i][j] = 0.0f;

    for (int k0 = 0; k0 < K; k0 += 16) {
#pragma unroll
        for (int l = 0; l < 2; l++) {
            int slot = tid + l * 256;
            int r = slot >> 2, c4 = slot & 3;
            float4 va = *reinterpret_cast<const float4*>(&A[(size_t)(bm + r) * K + k0 + c4 * 4]);
            As[c4 * 4 + 0][r] = va.x;
            As[c4 * 4 + 1][r] = va.y;
            As[c4 * 4 + 2][r] = va.z;
            As[c4 * 4 + 3][r] = va.w;
        }
#pragma unroll
        for (int l = 0; l < 2; l++) {
            int slot = tid + l * 256;
            int r = slot >> 2, c4 = slot & 3;
            float4 vb = *reinterpret_cast<const float4*>(&W[(size_t)(bn + r) * K + k0 + c4 * 4]);
            Bs[c4 * 4 + 0][r] = vb.x;
            Bs[c4 * 4 + 1][r] = vb.y;
            Bs[c4 * 4 + 2][r] = vb.z;
            Bs[c4 * 4 + 3][r] = vb.w;
        }
        __syncthreads();
#pragma unroll
        for (int kk = 0; kk < 16; kk++) {
            float4 a0 = *reinterpret_cast<const float4*>(&As[kk][ty * 8]);
            float4 a1 = *reinterpret_cast<const float4*>(&As[kk][ty * 8 + 4]);
            float4 b0 = *reinterpret_cast<const float4*>(&Bs[kk][tx * 8]);
            float4 b1 = *reinterpret_cast<const float4*>(&Bs[kk][tx * 8 + 4]);
            float a[8] = {a0.x, a0.y, a0.z, a0.w, a1.x, a1.y, a1.z, a1.w};
            float b[8] = {b0.x, b0.y, b0.z, b0.w, b1.x, b1.y, b1.z, b1.w};
#pragma unroll
            for (int i = 0; i < 8; i++)
#pragma unroll
                for (int j = 0; j < 8; j++)
                    acc[i][j] = fmaf(a[i], b[j], acc[i][j]);
        }
        __syncthreads();
    }
#pragma unroll
    for (int i = 0; i < 8; i++) {
        int m = bm + ty * 8 + i;
        size_t row = transOut ? ((size_t)(m & (Bq - 1)) * Sq + (m >> 8)) : (size_t)m;
        float4 o0 = make_float4(acc[i][0], acc[i][1], acc[i][2], acc[i][3]);
        float4 o1 = make_float4(acc[i][4], acc[i][5], acc[i][6], acc[i][7]);
        *reinterpret_cast<float4*>(&C[row * N + bn + tx * 8]) = o0;
        *reinterpret_cast<float4*>(&C[row * N + bn + tx * 8 + 4]) = o1;
    }
}

__global__ __launch_bounds__(256) void k_final(float* __restrict__ out) {
    int i = blockIdx.x * 256 + threadIdx.x;
    const int NLP = Bq * (Sq - 1);
    if (i < NLP) {
        int b = i / (Sq - 1), t = i % (Sq - 1);
        out[i] = d_lp[(size_t)t * Bq + b];
    } else if (i < NLP + Bq * Sq) {
        int j = i - NLP;
        int b = j >> 9, s = j & (Sq - 1);
        out[i] = (s == 0) ? 0.0f : (float)d_idx[(size_t)(s - 1) * Bq + b];
    }
}

// ---------------- host ----------------
extern "C" void kernel_launch(void* const* d_in, const int* in_sizes, int n_in,
                              void* d_out, int out_size) {
    const float* inputs   = (const float*)d_in[0];
    const float* W_embed  = (const float*)d_in[1];
    const float* enc_Wih  = (const float*)d_in[2];
    const float* enc_Whh  = (const float*)d_in[3];
    const float* enc_bih  = (const float*)d_in[4];
    const float* enc_bhh  = (const float*)d_in[5];
    const float* dec_Wih  = (const float*)d_in[6];
    const float* dec_Whh  = (const float*)d_in[7];
    const float* dec_bih  = (const float*)d_in[8];
    const float* dec_bhh  = (const float*)d_in[9];
    const float* Wq       = (const float*)d_in[10];
    const float* Wref     = (const float*)d_in[11];
    const float* v        = (const float*)d_in[12];

    float *p_emb, *p_Xg, *p_Dg, *p_enc, *p_rp;
    cudaGetSymbolAddress((void**)&p_emb, d_emb);
    cudaGetSymbolAddress((void**)&p_Xg, d_XgEnc);
    cudaGetSymbolAddress((void**)&p_Dg, d_Dg);
    cudaGetSymbolAddress((void**)&p_enc, d_encout);
    cudaGetSymbolAddress((void**)&p_rp, d_refproj);

    k_init<<<512, 256>>>();
    k_embed<<<(Sq * Bq * Eq) / 256, 256>>>(inputs, W_embed);

    const int Mbig = Sq * Bq;  // 131072
    {
        dim3 grid(G4 / 128, Mbig / 128);
        k_gemm2<<<grid, 256>>>(p_emb, enc_Wih, p_Xg, Mbig, G4, Eq, 0);
    }
    {
        dim3 grid(G4 / 128, Mbig / 128);
        k_gemm2<<<grid, 256>>>(p_emb, dec_Wih, p_Dg, Mbig, G4, Eq, 0);
    }

    k_encoder<<<NB_ENC, 256>>>(enc_Whh, enc_bih, enc_bhh);

    {
        // ref_proj written transposed: [b][s][h]
        dim3 grid(Hq / 128, Mbig / 128);
        k_gemm2<<<grid, 256>>>(p_enc, Wref, p_rp, Mbig, Hq, Hq, 1);
    }

    k_decoder<<<NB_DEC, 256>>>(dec_Whh, dec_bih, dec_bhh, Wq, v);

    k_final<<<(Bq * (Sq - 1) + Bq * Sq + 255) / 256, 256>>>((float*)d_out);
}

// round 7
// speedup vs baseline: 2.5461x; 1.0885x over previous
#include <cuda_runtime.h>
#include <cstdint>

#define Bq 256
#define Sq 512
#define Eq 256
#define Hq 256
#define G4 1024
#define NB_ENC 128
#define NB_DEC 256
#define MASKVAL -100000.0f
#define TINYF 1.17549435e-38f

// ---------------- device globals (static scratch) ----------------
__device__ float d_emb[(size_t)Sq * Bq * Eq];        // [s][b][e]
__device__ float d_XgEnc[(size_t)Sq * Bq * G4];      // [s][b][j]
__device__ float d_Dg[(size_t)Sq * Bq * G4];         // [s][b][j]
__device__ float d_encout[(size_t)Sq * Bq * Hq];     // [s][b][h]
__device__ float d_refproj[(size_t)Bq * Sq * Hq];    // [b][s][h]
__device__ float d_gum[(size_t)(Sq - 1) * Bq * Sq];  // [t][b][s] precomputed gumbel
__device__ float d_hbuf[2 * Bq * Hq];
__device__ float d_c[Bq * Hq];
__device__ float d_q[Bq * Hq];
__device__ int d_plist[Bq * Sq];                     // per-b candidate list
__device__ int d_ppos[Bq * Sq];                      // s -> slot
__device__ int d_chosen[Bq];
__device__ unsigned int d_keys[(Sq - 1) * 2];
__device__ float d_lp[(Sq - 1) * Bq];
__device__ int d_idx[(Sq - 1) * Bq];
__device__ unsigned int g_cnt = 0;
__device__ unsigned int g_gen = 0;

// ---------------- math helpers (XLA f32 semantics) ----------------
__device__ __forceinline__ float xtanh(float x) {
    float ax = fabsf(x);
    float xc = fminf(fmaxf(x, -7.90531110763549805f), 7.90531110763549805f);
    float x2 = xc * xc;
    float p = -2.76076847742355e-16f;
    p = fmaf(p, x2, 2.00018790482477e-13f);
    p = fmaf(p, x2, -8.60467152213735e-11f);
    p = fmaf(p, x2, 5.12229709037114e-08f);
    p = fmaf(p, x2, 1.48572235717979e-05f);
    p = fmaf(p, x2, 6.37261928875436e-04f);
    p = fmaf(p, x2, 4.89352455891786e-03f);
    float q = 1.19825839466702e-06f;
    q = fmaf(q, x2, 1.18534705686654e-04f);
    q = fmaf(q, x2, 2.26843463243900e-03f);
    q = fmaf(q, x2, 4.89352518554385e-03f);
    float t = (xc * p) / q;
    return (ax < 0.0004f) ? x : t;
}

__device__ __forceinline__ float xsigmoid(float x) {
    return 1.0f / (1.0f + expf(-x));
}

__device__ __forceinline__ unsigned int rotl32(unsigned int v, int r) {
    return (v << r) | (v >> (32 - r));
}

__device__ __forceinline__ void threefry2x32(unsigned int k0, unsigned int k1,
                                             unsigned int x0, unsigned int x1,
                                             unsigned int& o0, unsigned int& o1) {
    unsigned int ks2 = k0 ^ k1 ^ 0x1BD11BDAu;
    x0 += k0; x1 += k1;
#define TF_RND(r) { x0 += x1; x1 = rotl32(x1, r); x1 ^= x0; }
    TF_RND(13) TF_RND(15) TF_RND(26) TF_RND(6)
    x0 += k1; x1 += ks2 + 1u;
    TF_RND(17) TF_RND(29) TF_RND(16) TF_RND(24)
    x0 += ks2; x1 += k0 + 2u;
    TF_RND(13) TF_RND(15) TF_RND(26) TF_RND(6)
    x0 += k0; x1 += k1 + 3u;
    TF_RND(17) TF_RND(29) TF_RND(16) TF_RND(24)
    x0 += k1; x1 += ks2 + 4u;
    TF_RND(13) TF_RND(15) TF_RND(26) TF_RND(6)
    x0 += ks2; x1 += k0 + 5u;
#undef TF_RND
    o0 = x0; o1 = x1;
}

__device__ __forceinline__ unsigned int tf_bits32(unsigned int k0, unsigned int k1,
                                                  unsigned int idx) {
    unsigned int o0, o1;
    threefry2x32(k0, k1, 0u, idx, o0, o1);
    return o0 ^ o1;
}

__device__ __forceinline__ float gumbel_from_bits(unsigned int bits) {
    float f = __uint_as_float((bits >> 9) | 0x3f800000u) - 1.0f;
    float u = f + TINYF;
    u = fmaxf(TINYF, u);
    return -logf(-logf(u));
}

// ---------------- grid-wide barrier (volatile spin, atomic arrive) ----------------
template <int NBLK>
__device__ __forceinline__ void gsync(unsigned int& gen) {
    __syncthreads();
    if (threadIdx.x == 0) {
        __threadfence();
        unsigned int t = atomicAdd(&g_cnt, 1u);
        if (t == NBLK - 1) {
            atomicExch(&g_cnt, 0u);
            __threadfence();
            atomicExch(&g_gen, gen + 1);
        } else {
            volatile unsigned int* p = &g_gen;
            while ((int)(*p - (gen + 1)) < 0) { }
            __threadfence();
        }
    }
    gen++;
    __syncthreads();
}

// ---------------- fused gates-GEMM + LSTM cell (one step, 128 working blocks) ----------------
__device__ __forceinline__ void lstm_phase(
    int bid, int tid,
    const float* __restrict__ hin, float* __restrict__ hout,
    const float* __restrict__ Whh, const float* __restrict__ bih,
    const float* __restrict__ bhh,
    const float* __restrict__ xg,
    const int* __restrict__ gIdx,
    float* __restrict__ encout,
    float (*As)[34], float (*Bs)[68])
{
    int tb = bid >> 4, th = bid & 15;
    int bm = tb * 32, h0 = th * 16;
    int tx = tid & 15, ty = tid >> 4;
    float acc[2][4];
#pragma unroll
    for (int i = 0; i < 2; i++)
#pragma unroll
        for (int g = 0; g < 4; g++) acc[i][g] = 0.0f;

    for (int k0 = 0; k0 < Hq; k0 += 16) {
#pragma unroll
        for (int l = 0; l < 2; l++) {
            int idx = tid + l * 256;
            int m = idx >> 4, kk = idx & 15;
            As[kk][m] = hin[(bm + m) * Hq + k0 + kk];
        }
#pragma unroll
        for (int l = 0; l < 4; l++) {
            int idx = tid + l * 256;
            int c = idx >> 4, kk = idx & 15;
            int h = c >> 2, g = c & 3;
            Bs[kk][c] = Whh[(g * Hq + h0 + h) * Hq + k0 + kk];
        }
        __syncthreads();
#pragma unroll
        for (int kk = 0; kk < 16; kk++) {
            float2 a2 = *reinterpret_cast<const float2*>(&As[kk][ty * 2]);
            float4 b4 = *reinterpret_cast<const float4*>(&Bs[kk][tx * 4]);
            acc[0][0] = fmaf(a2.x, b4.x, acc[0][0]);
            acc[0][1] = fmaf(a2.x, b4.y, acc[0][1]);
            acc[0][2] = fmaf(a2.x, b4.z, acc[0][2]);
            acc[0][3] = fmaf(a2.x, b4.w, acc[0][3]);
            acc[1][0] = fmaf(a2.y, b4.x, acc[1][0]);
            acc[1][1] = fmaf(a2.y, b4.y, acc[1][1]);
            acc[1][2] = fmaf(a2.y, b4.z, acc[1][2]);
            acc[1][3] = fmaf(a2.y, b4.w, acc[1][3]);
        }
        __syncthreads();
    }

    int h = h0 + tx;
#pragma unroll
    for (int i = 0; i < 2; i++) {
        int b = bm + ty * 2 + i;
        size_t xrow;
        if (gIdx) xrow = ((size_t)gIdx[b] * Bq + b) * G4;
        else      xrow = (size_t)b * G4;
        float gi = acc[i][0] + xg[xrow + h]          + bih[h]          + bhh[h];
        float gf = acc[i][1] + xg[xrow + Hq + h]     + bih[Hq + h]     + bhh[Hq + h];
        float gg = acc[i][2] + xg[xrow + 2*Hq + h]   + bih[2*Hq + h]   + bhh[2*Hq + h];
        float go = acc[i][3] + xg[xrow + 3*Hq + h]   + bih[3*Hq + h]   + bhh[3*Hq + h];
        int idx = b * Hq + h;
        float cc = d_c[idx];
        float cn = xsigmoid(gf) * cc + xsigmoid(gi) * xtanh(gg);
        float hn = xsigmoid(go) * xtanh(cn);
        d_c[idx] = cn;
        hout[idx] = hn;
        if (encout) encout[idx] = hn;
    }
}

// ---------------- persistent encoder (128 blocks) ----------------
__global__ __launch_bounds__(256, 1) void k_encoder(const float* __restrict__ Whh,
                                                    const float* __restrict__ bih,
                                                    const float* __restrict__ bhh) {
    __shared__ float As[16][34];
    __shared__ float Bs[16][68];
    __shared__ unsigned int s_gen0;
    int tid = threadIdx.x, bid = blockIdx.x;
    if (tid == 0) s_gen0 = atomicAdd(&g_gen, 0u);
    __syncthreads();
    unsigned int gen = s_gen0;

    for (int s = 0; s < Sq; s++) {
        const float* hin = d_hbuf + (s & 1) * (Bq * Hq);
        float* hout = d_hbuf + ((s & 1) ^ 1) * (Bq * Hq);
        lstm_phase(bid, tid, hin, hout, Whh, bih, bhh,
                   d_XgEnc + (size_t)s * Bq * G4, nullptr,
                   d_encout + (size_t)s * Bq * Hq, As, Bs);
        gsync<NB_ENC>(gen);
    }
}

// ---------------- persistent decoder (256 blocks, 2 CTA/SM) ----------------
__global__ __launch_bounds__(256, 2) void k_decoder(const float* __restrict__ Whh,
                                                    const float* __restrict__ bih,
                                                    const float* __restrict__ bhh,
                                                    const float* __restrict__ Wq,
                                                    const float* __restrict__ vvec) {
    __shared__ float As[16][34];
    __shared__ float Bs[16][68];
    __shared__ float qs[Hq];
    __shared__ float vsm[Hq];
    __shared__ float ls[Sq];
    __shared__ float rv[256];
    __shared__ int   ri[256];
    __shared__ float sv[256];
    __shared__ unsigned int s_gen0;

    int tid = threadIdx.x, bid = blockIdx.x;
    if (tid == 0) s_gen0 = atomicAdd(&g_gen, 0u);
    vsm[tid] = vvec[tid];
    __syncthreads();
    unsigned int gen = s_gen0;

    int tb = bid >> 4, th = bid & 15;
    int bm = tb * 32, h0 = th * 16;
    int tx = tid & 15, ty = tid >> 4;
    int w = tid >> 5, lane = tid & 31;
    int b = bid;  // phase C batch row

    const float4* vs4 = reinterpret_cast<const float4*>(vsm);

    for (int t = 0; t < Sq - 1; t++) {
        const float* hin = d_hbuf + (t & 1) * (Bq * Hq);
        float* hout = d_hbuf + ((t & 1) ^ 1) * (Bq * Hq);

        // Phase A: gates GEMM + cell (blocks 0..127)
        if (bid < 128)
            lstm_phase(bid, tid, hin, hout, Whh, bih, bhh, d_Dg, d_chosen, nullptr, As, Bs);
        gsync<NB_DEC>(gen);

        // Phase B: q = h_new @ Wq^T (blocks 0..127)
        if (bid < 128) {
            float acc0 = 0.0f, acc1 = 0.0f;
            for (int k0 = 0; k0 < Hq; k0 += 16) {
#pragma unroll
                for (int l = 0; l < 2; l++) {
                    int idx = tid + l * 256;
                    int m = idx >> 4, kk = idx & 15;
                    As[kk][m] = hout[(bm + m) * Hq + k0 + kk];
                }
                {
                    int hh = tid >> 4, kk = tid & 15;
                    Bs[kk][hh] = Wq[(h0 + hh) * Hq + k0 + kk];
                }
                __syncthreads();
#pragma unroll
                for (int kk = 0; kk < 16; kk++) {
                    float2 a2 = *reinterpret_cast<const float2*>(&As[kk][ty * 2]);
                    float bq = Bs[kk][tx];
                    acc0 = fmaf(a2.x, bq, acc0);
                    acc1 = fmaf(a2.y, bq, acc1);
                }
                __syncthreads();
            }
            d_q[(bm + ty * 2) * Hq + h0 + tx] = acc0;
            d_q[(bm + ty * 2 + 1) * Hq + h0 + tx] = acc1;
        }
        gsync<NB_DEC>(gen);

        // Phase C: attention logits over candidate list + gumbel argmax + log-softmax
        {
            int n = Sq - 1 - t;                          // candidates remaining
            const float* gum = d_gum + ((size_t)t * Bq + b) * Sq;
            qs[tid] = d_q[b * Hq + tid];
            ls[tid] = MASKVAL;
            ls[tid + 256] = MASKVAL;
            __syncthreads();
            const float4* qs4 = reinterpret_cast<const float4*>(qs);
            float4 q0 = qs4[lane], q1 = qs4[lane + 32];
            float4 v0 = vs4[lane], v1 = vs4[lane + 32];
            const int* lst = d_plist + b * Sq;
            const float* rbase = d_refproj + (size_t)b * Sq * Hq;

            for (int k0 = w * 4; k0 < n; k0 += 32) {
                int sx[4];
                sx[0] = lst[k0];
                sx[1] = (k0 + 1 < n) ? lst[k0 + 1] : -1;
                sx[2] = (k0 + 2 < n) ? lst[k0 + 2] : -1;
                sx[3] = (k0 + 3 < n) ? lst[k0 + 3] : -1;
                float4 ra[4], rb[4];
#pragma unroll
                for (int j = 0; j < 4; j++) {
                    if (sx[j] >= 0) {
                        const float4* p = reinterpret_cast<const float4*>(
                            rbase + (size_t)sx[j] * Hq);
                        ra[j] = p[lane];
                        rb[j] = p[lane + 32];
                    }
                }
                float sums[4] = {0.0f, 0.0f, 0.0f, 0.0f};
#pragma unroll
                for (int j = 0; j < 4; j++) {
                    if (sx[j] >= 0) {
                        float s = 0.0f;
                        s = fmaf(v0.x, xtanh(q0.x + ra[j].x), s);
                        s = fmaf(v0.y, xtanh(q0.y + ra[j].y), s);
                        s = fmaf(v0.z, xtanh(q0.z + ra[j].z), s);
                        s = fmaf(v0.w, xtanh(q0.w + ra[j].w), s);
                        s = fmaf(v1.x, xtanh(q1.x + rb[j].x), s);
                        s = fmaf(v1.y, xtanh(q1.y + rb[j].y), s);
                        s = fmaf(v1.z, xtanh(q1.z + rb[j].z), s);
                        s = fmaf(v1.w, xtanh(q1.w + rb[j].w), s);
                        sums[j] = s;
                    }
                }
#pragma unroll
                for (int off = 16; off > 0; off >>= 1) {
                    sums[0] += __shfl_down_sync(0xffffffffu, sums[0], off);
                    sums[1] += __shfl_down_sync(0xffffffffu, sums[1], off);
                    sums[2] += __shfl_down_sync(0xffffffffu, sums[2], off);
                    sums[3] += __shfl_down_sync(0xffffffffu, sums[3], off);
                }
                if (lane == 0) {
#pragma unroll
                    for (int j = 0; j < 4; j++)
                        if (sx[j] >= 0) ls[sx[j]] = sums[j];
                }
            }
            __syncthreads();

            // candidate value = logit + precomputed gumbel (masked -> -inf)
            float out2[2];
#pragma unroll
            for (int u = 0; u < 2; u++) {
                int s = tid + (u << 8);
                float logit = ls[s];
                out2[u] = (logit == MASKVAL) ? -1e30f : logit + gum[s];
            }
            __syncthreads();

            // argmax (tie -> smaller index)
            float bv; int bi;
            if (out2[0] >= out2[1]) { bv = out2[0]; bi = tid; }
            else { bv = out2[1]; bi = tid + 256; }
            rv[tid] = bv; ri[tid] = bi;
            __syncthreads();
            for (int off = 128; off > 0; off >>= 1) {
                if (tid < off) {
                    float v2 = rv[tid + off]; int i2 = ri[tid + off];
                    if (v2 > rv[tid] || (v2 == rv[tid] && i2 < ri[tid])) {
                        rv[tid] = v2; ri[tid] = i2;
                    }
                }
                __syncthreads();
            }
            int ch = ri[0];
            __syncthreads();

            // log-softmax of masked logits
            rv[tid] = fmaxf(ls[tid], ls[tid + 256]);
            __syncthreads();
            for (int off = 128; off > 0; off >>= 1) {
                if (tid < off) rv[tid] = fmaxf(rv[tid], rv[tid + off]);
                __syncthreads();
            }
            float m = rv[0];
            sv[tid] = expf(ls[tid] - m) + expf(ls[tid + 256] - m);
            __syncthreads();
            for (int off = 128; off > 0; off >>= 1) {
                if (tid < off) sv[tid] += sv[tid + off];
                __syncthreads();
            }
            if (tid == 0) {
                float lp = (ls[ch] - m) - logf(sv[0]);
                d_lp[(size_t)t * Bq + b] = lp;
                d_idx[(size_t)t * Bq + b] = ch;
                d_chosen[b] = ch;
                // remove ch from candidate list (O(1) swap-with-last)
                int base = b * Sq;
                int kk = d_ppos[base + ch];
                int sl = d_plist[base + n - 1];
                d_plist[base + kk] = sl;
                d_ppos[base + sl] = kk;
            }
            __syncthreads();
        }
        gsync<NB_DEC>(gen);
    }
}

// ---------------- init (+ threefry keys, partitionable split; candidate lists) ----------------
__global__ __launch_bounds__(256) void k_init() {
    int i = blockIdx.x * 256 + threadIdx.x;   // covers 131072
    if (i < 2 * Bq * Hq) d_hbuf[i] = 0.0f;
    if (i < Bq * Hq) d_c[i] = 0.0f;
    if (i < Bq * Sq) {
        int bb = i >> 9, s = i & (Sq - 1);
        if (s > 0) {
            d_plist[bb * Sq + (s - 1)] = s;
            d_ppos[bb * Sq + s] = s - 1;
        } else {
            d_ppos[bb * Sq] = -1;
        }
    }
    if (i < Bq) d_chosen[i] = 0;
    if (i < (Sq - 1)) {
        unsigned int o0, o1;
        threefry2x32(0u, 1u, 0u, (unsigned int)i, o0, o1);
        d_keys[2 * i] = o0;
        d_keys[2 * i + 1] = o1;
    }
}

// ---------------- precompute all gumbel noise ----------------
__global__ __launch_bounds__(256) void k_gum() {
    size_t g = (size_t)blockIdx.x * 256 + threadIdx.x;  // (Sq-1)*Bq*Sq elements
    int t = (int)(g >> 17);
    if (t >= Sq - 1) return;
    unsigned int r = (unsigned int)(g & 131071u);
    unsigned int bits = tf_bits32(d_keys[2 * t], d_keys[2 * t + 1], r);
    d_gum[g] = gumbel_from_bits(bits);
}

__global__ __launch_bounds__(256) void k_embed(const float* __restrict__ inputs,
                                               const float* __restrict__ W_embed) {
    int i = blockIdx.x * 256 + threadIdx.x;
    int e = i & (Eq - 1);
    int b = (i >> 8) & (Bq - 1);
    int s = i >> 16;
    const float* inp = inputs + ((size_t)b * Sq + s) * 2;
    d_emb[i] = fmaf(inp[1], W_embed[Eq + e], inp[0] * W_embed[e]);
}

// ---------------- big tiled GEMM: C = A[M][K] * W[N][K]^T ; 128x128x16, 8x8 ----------------
__global__ __launch_bounds__(256) void k_gemm2(const float* __restrict__ A,
                                               const float* __restrict__ W,
                                               float* __restrict__ C,
                                               int M, int N, int K, int transOut) {
    __shared__ float As[16][136];
    __shared__ float Bs[16][136];
    int bm = blockIdx.y * 128, bn = blockIdx.x * 128;
    int tid = threadIdx.x;
    int tx = tid & 15, ty = tid >> 4;
    float acc[8][8];
#pragma unroll
    for (int i = 0; i < 8; i++)
#pragma unroll
        for (int j = 0; j < 8; j++) acc[i][j] = 0.0f;

    for (int k0 = 0; k0 < K; k0 += 16) {
#pragma unroll
        for (int l = 0; l < 2; l++) {
            int slot = tid + l * 256;
            int r = slot >> 2, c4 = slot & 3;
            float4 va = *reinterpret_cast<const float4*>(&A[(size_t)(bm + r) * K + k0 + c4 * 4]);
            As[c4 * 4 + 0][r] = va.x;
            As[c4 * 4 + 1][r] = va.y;
            As[c4 * 4 + 2][r] = va.z;
            As[c4 * 4 + 3][r] = va.w;
        }
#pragma unroll
        for (int l = 0; l < 2; l++) {
            int slot = tid + l * 256;
            int r = slot >> 2, c4 = slot & 3;
            float4 vb = *reinterpret_cast<const float4*>(&W[(size_t)(bn + r) * K + k0 + c4 * 4]);
            Bs[c4 * 4 + 0][r] = vb.x;
            Bs[c4 * 4 + 1][r] = vb.y;
            Bs[c4 * 4 + 2][r] = vb.z;
            Bs[c4 * 4 + 3][r] = vb.w;
        }
        __syncthreads();
#pragma unroll
        for (int kk = 0; kk < 16; kk++) {
            float4 a0 = *reinterpret_cast<const float4*>(&As[kk][ty * 8]);
            float4 a1 = *reinterpret_cast<const float4*>(&As[kk][ty * 8 + 4]);
            float4 b0 = *reinterpret_cast<const float4*>(&Bs[kk][tx * 8]);
            float4 b1 = *reinterpret_cast<const float4*>(&Bs[kk][tx * 8 + 4]);
            float a[8] = {a0.x, a0.y, a0.z, a0.w, a1.x, a1.y, a1.z, a1.w};
            float b[8] = {b0.x, b0.y, b0.z, b0.w, b1.x, b1.y, b1.z, b1.w};
#pragma unroll
            for (int i = 0; i < 8; i++)
#pragma unroll
                for (int j = 0; j < 8; j++)
                    acc[i][j] = fmaf(a[i], b[j], acc[i][j]);
        }
        __syncthreads();
    }
#pragma unroll
    for (int i = 0; i < 8; i++) {
        int m = bm + ty * 8 + i;
        size_t row = transOut ? ((size_t)(m & (Bq - 1)) * Sq + (m >> 8)) : (size_t)m;
        float4 o0 = make_float4(acc[i][0], acc[i][1], acc[i][2], acc[i][3]);
        float4 o1 = make_float4(acc[i][4], acc[i][5], acc[i][6], acc[i][7]);
        *reinterpret_cast<float4*>(&C[row * N + bn + tx * 8]) = o0;
        *reinterpret_cast<float4*>(&C[row * N + bn + tx * 8 + 4]) = o1;
    }
}

__global__ __launch_bounds__(256) void k_final(float* __restrict__ out) {
    int i = blockIdx.x * 256 + threadIdx.x;
    const int NLP = Bq * (Sq - 1);
    if (i < NLP) {
        int b = i / (Sq - 1), t = i % (Sq - 1);
        out[i] = d_lp[(size_t)t * Bq + b];
    } else if (i < NLP + Bq * Sq) {
        int j = i - NLP;
        int b = j >> 9, s = j & (Sq - 1);
        out[i] = (s == 0) ? 0.0f : (float)d_idx[(size_t)(s - 1) * Bq + b];
    }
}

// ---------------- host ----------------
extern "C" void kernel_launch(void* const* d_in, const int* in_sizes, int n_in,
                              void* d_out, int out_size) {
    const float* inputs   = (const float*)d_in[0];
    const float* W_embed  = (const float*)d_in[1];
    const float* enc_Wih  = (const float*)d_in[2];
    const float* enc_Whh  = (const float*)d_in[3];
    const float* enc_bih  = (const float*)d_in[4];
    const float* enc_bhh  = (const float*)d_in[5];
    const float* dec_Wih  = (const float*)d_in[6];
    const float* dec_Whh  = (const float*)d_in[7];
    const float* dec_bih  = (const float*)d_in[8];
    const float* dec_bhh  = (const float*)d_in[9];
    const float* Wq       = (const float*)d_in[10];
    const float* Wref     = (const float*)d_in[11];
    const float* v        = (const float*)d_in[12];

    float *p_emb, *p_Xg, *p_Dg, *p_enc, *p_rp;
    cudaGetSymbolAddress((void**)&p_emb, d_emb);
    cudaGetSymbolAddress((void**)&p_Xg, d_XgEnc);
    cudaGetSymbolAddress((void**)&p_Dg, d_Dg);
    cudaGetSymbolAddress((void**)&p_enc, d_encout);
    cudaGetSymbolAddress((void**)&p_rp, d_refproj);

    k_init<<<512, 256>>>();

    // precompute gumbel noise for all (t, b, s): 511 * 131072 elements
    {
        size_t total = (size_t)(Sq - 1) * Bq * Sq;
        k_gum<<<(unsigned int)((total + 255) / 256), 256>>>();
    }

    k_embed<<<(Sq * Bq * Eq) / 256, 256>>>(inputs, W_embed);

    const int Mbig = Sq * Bq;  // 131072
    {
        dim3 grid(G4 / 128, Mbig / 128);
        k_gemm2<<<grid, 256>>>(p_emb, enc_Wih, p_Xg, Mbig, G4, Eq, 0);
    }
    {
        dim3 grid(G4 / 128, Mbig / 128);
        k_gemm2<<<grid, 256>>>(p_emb, dec_Wih, p_Dg, Mbig, G4, Eq, 0);
    }

    k_encoder<<<NB_ENC, 256>>>(enc_Whh, enc_bih, enc_bhh);

    {
        // ref_proj written transposed: [b][s][h]
        dim3 grid(Hq / 128, Mbig / 128);
        k_gemm2<<<grid, 256>>>(p_enc, Wref, p_rp, Mbig, Hq, Hq, 1);
    }

    k_decoder<<<NB_DEC, 256>>>(dec_Whh, dec_bih, dec_bhh, Wq, v);

    k_final<<<(Bq * (Sq - 1) + Bq * Sq + 255) / 256, 256>>>((float*)d_out);
}

// round 8
// speedup vs baseline: 2.6477x; 1.0399x over previous
#include <cuda_runtime.h>
#include <cstdint>

#define Bq 256
#define Sq 512
#define Eq 256
#define Hq 256
#define G4 1024
#define NB_ENC 128
#define NB_DEC 256
#define MASKVAL -100000.0f
#define TINYF 1.17549435e-38f

// ---------------- device globals (static scratch) ----------------
__device__ float d_emb[(size_t)Sq * Bq * Eq];        // [s][b][e]
__device__ float d_XgEnc[(size_t)Sq * Bq * G4];      // [s][b][j]
__device__ float d_Dg[(size_t)Sq * Bq * G4];         // [s][b][j]
__device__ float d_encout[(size_t)Sq * Bq * Hq];     // [s][b][h]
__device__ float d_refproj[(size_t)Bq * Sq * Hq];    // [b][s][h]
__device__ float d_gum[(size_t)(Sq - 1) * Bq * Sq];  // [t][b][s]
__device__ float d_WqT[Hq * Hq];                     // [k][h]
__device__ float d_hbuf[2 * Bq * Hq];
__device__ float d_c[Bq * Hq];
__device__ int d_plist[Bq * Sq];
__device__ int d_ppos[Bq * Sq];
__device__ int d_chosen[Bq];
__device__ unsigned int d_keys[(Sq - 1) * 2];
__device__ float d_lp[(Sq - 1) * Bq];
__device__ int d_idx[(Sq - 1) * Bq];
__device__ unsigned int g_cnt = 0;
__device__ unsigned int g_gen = 0;

// ---------------- f32x2 packed helpers (each half rounds RN independently) ----------------
__device__ __forceinline__ unsigned long long pk2(float lo, float hi) {
    unsigned long long r;
    asm("mov.b64 %0, {%1, %2};" : "=l"(r) : "f"(lo), "f"(hi));
    return r;
}
__device__ __forceinline__ void upk2(unsigned long long v, float& lo, float& hi) {
    asm("mov.b64 {%0, %1}, %2;" : "=f"(lo), "=f"(hi) : "l"(v));
}
__device__ __forceinline__ unsigned long long fma2(unsigned long long a,
                                                   unsigned long long b,
                                                   unsigned long long c) {
    unsigned long long d;
    asm("fma.rn.f32x2 %0, %1, %2, %3;" : "=l"(d) : "l"(a), "l"(b), "l"(c));
    return d;
}
__device__ __forceinline__ unsigned long long mul2(unsigned long long a,
                                                   unsigned long long b) {
    unsigned long long d;
    asm("mul.rn.f32x2 %0, %1, %2;" : "=l"(d) : "l"(a), "l"(b));
    return d;
}
__device__ __forceinline__ unsigned long long pk1(float c) { return pk2(c, c); }

// ---------------- math helpers (XLA f32 semantics) ----------------
__device__ __forceinline__ float xtanh(float x) {
    float ax = fabsf(x);
    float xc = fminf(fmaxf(x, -7.90531110763549805f), 7.90531110763549805f);
    float x2 = xc * xc;
    float p = -2.76076847742355e-16f;
    p = fmaf(p, x2, 2.00018790482477e-13f);
    p = fmaf(p, x2, -8.60467152213735e-11f);
    p = fmaf(p, x2, 5.12229709037114e-08f);
    p = fmaf(p, x2, 1.48572235717979e-05f);
    p = fmaf(p, x2, 6.37261928875436e-04f);
    p = fmaf(p, x2, 4.89352455891786e-03f);
    float q = 1.19825839466702e-06f;
    q = fmaf(q, x2, 1.18534705686654e-04f);
    q = fmaf(q, x2, 2.26843463243900e-03f);
    q = fmaf(q, x2, 4.89352518554385e-03f);
    float t = (xc * p) / q;
    return (ax < 0.0004f) ? x : t;
}

// pairwise tanh: identical bits to xtanh per element
__device__ __forceinline__ void xtanh2(float x0, float x1, float& t0, float& t1) {
    const float CL = 7.90531110763549805f;
    float c0 = fminf(fmaxf(x0, -CL), CL);
    float c1 = fminf(fmaxf(x1, -CL), CL);
    unsigned long long xc = pk2(c0, c1);
    unsigned long long x2 = mul2(xc, xc);
    unsigned long long p = pk1(-2.76076847742355e-16f);
    p = fma2(p, x2, pk1(2.00018790482477e-13f));
    p = fma2(p, x2, pk1(-8.60467152213735e-11f));
    p = fma2(p, x2, pk1(5.12229709037114e-08f));
    p = fma2(p, x2, pk1(1.48572235717979e-05f));
    p = fma2(p, x2, pk1(6.37261928875436e-04f));
    p = fma2(p, x2, pk1(4.89352455891786e-03f));
    unsigned long long q = pk1(1.19825839466702e-06f);
    q = fma2(q, x2, pk1(1.18534705686654e-04f));
    q = fma2(q, x2, pk1(2.26843463243900e-03f));
    q = fma2(q, x2, pk1(4.89352518554385e-03f));
    unsigned long long num = mul2(xc, p);
    float n0, n1, q0, q1;
    upk2(num, n0, n1);
    upk2(q, q0, q1);
    float r0 = n0 / q0;
    float r1 = n1 / q1;
    t0 = (fabsf(x0) < 0.0004f) ? x0 : r0;
    t1 = (fabsf(x1) < 0.0004f) ? x1 : r1;
}

__device__ __forceinline__ float xsigmoid(float x) {
    return 1.0f / (1.0f + expf(-x));
}

__device__ __forceinline__ unsigned int rotl32(unsigned int v, int r) {
    return (v << r) | (v >> (32 - r));
}

__device__ __forceinline__ void threefry2x32(unsigned int k0, unsigned int k1,
                                             unsigned int x0, unsigned int x1,
                                             unsigned int& o0, unsigned int& o1) {
    unsigned int ks2 = k0 ^ k1 ^ 0x1BD11BDAu;
    x0 += k0; x1 += k1;
#define TF_RND(r) { x0 += x1; x1 = rotl32(x1, r); x1 ^= x0; }
    TF_RND(13) TF_RND(15) TF_RND(26) TF_RND(6)
    x0 += k1; x1 += ks2 + 1u;
    TF_RND(17) TF_RND(29) TF_RND(16) TF_RND(24)
    x0 += ks2; x1 += k0 + 2u;
    TF_RND(13) TF_RND(15) TF_RND(26) TF_RND(6)
    x0 += k0; x1 += k1 + 3u;
    TF_RND(17) TF_RND(29) TF_RND(16) TF_RND(24)
    x0 += k1; x1 += ks2 + 4u;
    TF_RND(13) TF_RND(15) TF_RND(26) TF_RND(6)
    x0 += ks2; x1 += k0 + 5u;
#undef TF_RND
    o0 = x0; o1 = x1;
}

__device__ __forceinline__ unsigned int tf_bits32(unsigned int k0, unsigned int k1,
                                                  unsigned int idx) {
    unsigned int o0, o1;
    threefry2x32(k0, k1, 0u, idx, o0, o1);
    return o0 ^ o1;
}

__device__ __forceinline__ float gumbel_from_bits(unsigned int bits) {
    float f = __uint_as_float((bits >> 9) | 0x3f800000u) - 1.0f;
    float u = f + TINYF;
    u = fmaxf(TINYF, u);
    return -logf(-logf(u));
}

// ---------------- grid-wide barrier ----------------
template <int NBLK>
__device__ __forceinline__ void gsync(unsigned int& gen) {
    __syncthreads();
    if (threadIdx.x == 0) {
        __threadfence();
        unsigned int t = atomicAdd(&g_cnt, 1u);
        if (t == NBLK - 1) {
            atomicExch(&g_cnt, 0u);
            __threadfence();
            atomicExch(&g_gen, gen + 1);
        } else {
            volatile unsigned int* p = &g_gen;
            while ((int)(*p - (gen + 1)) < 0) { }
            __threadfence();
        }
    }
    gen++;
    __syncthreads();
}

// ---------------- encoder lstm phase (128 blocks, 32b x 16h tiles) ----------------
__device__ __forceinline__ void lstm_phase_enc(
    int bid, int tid,
    const float* __restrict__ hin, float* __restrict__ hout,
    const float* __restrict__ Whh, const float* __restrict__ bih,
    const float* __restrict__ bhh,
    const float* __restrict__ xg,
    float* __restrict__ encout,
    float (*As)[34], float (*Bs)[68])
{
    int tb = bid >> 4, th = bid & 15;
    int bm = tb * 32, h0 = th * 16;
    int tx = tid & 15, ty = tid >> 4;
    float acc[2][4];
#pragma unroll
    for (int i = 0; i < 2; i++)
#pragma unroll
        for (int g = 0; g < 4; g++) acc[i][g] = 0.0f;

    for (int k0 = 0; k0 < Hq; k0 += 16) {
#pragma unroll
        for (int l = 0; l < 2; l++) {
            int idx = tid + l * 256;
            int m = idx >> 4, kk = idx & 15;
            As[kk][m] = hin[(bm + m) * Hq + k0 + kk];
        }
#pragma unroll
        for (int l = 0; l < 4; l++) {
            int idx = tid + l * 256;
            int c = idx >> 4, kk = idx & 15;
            int h = c >> 2, g = c & 3;
            Bs[kk][c] = Whh[(g * Hq + h0 + h) * Hq + k0 + kk];
        }
        __syncthreads();
#pragma unroll
        for (int kk = 0; kk < 16; kk++) {
            float2 a2 = *reinterpret_cast<const float2*>(&As[kk][ty * 2]);
            float4 b4 = *reinterpret_cast<const float4*>(&Bs[kk][tx * 4]);
            acc[0][0] = fmaf(a2.x, b4.x, acc[0][0]);
            acc[0][1] = fmaf(a2.x, b4.y, acc[0][1]);
            acc[0][2] = fmaf(a2.x, b4.z, acc[0][2]);
            acc[0][3] = fmaf(a2.x, b4.w, acc[0][3]);
            acc[1][0] = fmaf(a2.y, b4.x, acc[1][0]);
            acc[1][1] = fmaf(a2.y, b4.y, acc[1][1]);
            acc[1][2] = fmaf(a2.y, b4.z, acc[1][2]);
            acc[1][3] = fmaf(a2.y, b4.w, acc[1][3]);
        }
        __syncthreads();
    }

    int h = h0 + tx;
#pragma unroll
    for (int i = 0; i < 2; i++) {
        int b = bm + ty * 2 + i;
        size_t xrow = (size_t)b * G4;
        float gi = acc[i][0] + xg[xrow + h]          + bih[h]          + bhh[h];
        float gf = acc[i][1] + xg[xrow + Hq + h]     + bih[Hq + h]     + bhh[Hq + h];
        float gg = acc[i][2] + xg[xrow + 2*Hq + h]   + bih[2*Hq + h]   + bhh[2*Hq + h];
        float go = acc[i][3] + xg[xrow + 3*Hq + h]   + bih[3*Hq + h]   + bhh[3*Hq + h];
        int idx = b * Hq + h;
        float cc = d_c[idx];
        float cn = xsigmoid(gf) * cc + xsigmoid(gi) * xtanh(gg);
        float hn = xsigmoid(go) * xtanh(cn);
        d_c[idx] = cn;
        hout[idx] = hn;
        encout[idx] = hn;
    }
}

__global__ __launch_bounds__(256, 1) void k_encoder(const float* __restrict__ Whh,
                                                    const float* __restrict__ bih,
                                                    const float* __restrict__ bhh) {
    __shared__ float As[16][34];
    __shared__ float Bs[16][68];
    __shared__ unsigned int s_gen0;
    int tid = threadIdx.x, bid = blockIdx.x;
    if (tid == 0) s_gen0 = atomicAdd(&g_gen, 0u);
    __syncthreads();
    unsigned int gen = s_gen0;

    for (int s = 0; s < Sq; s++) {
        const float* hin = d_hbuf + (s & 1) * (Bq * Hq);
        float* hout = d_hbuf + ((s & 1) ^ 1) * (Bq * Hq);
        lstm_phase_enc(bid, tid, hin, hout, Whh, bih, bhh,
                       d_XgEnc + (size_t)s * Bq * G4,
                       d_encout + (size_t)s * Bq * Hq, As, Bs);
        gsync<NB_ENC>(gen);
    }
}

// ---------------- persistent decoder: 256 blocks, 2 CTA/SM, 2 phases/step ----------------
__global__ __launch_bounds__(256, 2) void k_decoder(const float* __restrict__ Whh,
                                                    const float* __restrict__ bih,
                                                    const float* __restrict__ bhh,
                                                    const float* __restrict__ vvec) {
    __shared__ float As[16][17];
    __shared__ float Bs[16][68];
    __shared__ __align__(16) float hs[Hq];
    __shared__ __align__(16) float qs[Hq];
    __shared__ __align__(16) float vsm[Hq];
    __shared__ __align__(16) float ls[Sq];
    __shared__ float rv[8];
    __shared__ int   ri[8];
    __shared__ float sv[8];
    __shared__ int   s_ch;
    __shared__ unsigned int s_gen0;

    int tid = threadIdx.x, bid = blockIdx.x;
    if (tid == 0) s_gen0 = atomicAdd(&g_gen, 0u);
    vsm[tid] = vvec[tid];
    __syncthreads();
    unsigned int gen = s_gen0;

    // phase A tiling: 256 blocks = 16 (b-tiles) x 16 (h-tiles); tile 16 b x 16 h x 4 g
    int tbA = bid >> 4, thA = bid & 15;
    int bmA = tbA * 16, h0A = thA * 16;
    int txA = tid & 15, tyA = tid >> 4;
    int w = tid >> 5, lane = tid & 31;
    int b = bid;  // phase C batch row

    const float4* vs4 = reinterpret_cast<const float4*>(vsm);

    for (int t = 0; t < Sq - 1; t++) {
        const float* hin = d_hbuf + (t & 1) * (Bq * Hq);
        float* hout = d_hbuf + ((t & 1) ^ 1) * (Bq * Hq);

        // ---- Phase A: gates GEMM + LSTM cell (all 256 blocks) ----
        {
            float acc[4] = {0.0f, 0.0f, 0.0f, 0.0f};
            for (int k0 = 0; k0 < Hq; k0 += 16) {
                As[tid & 15][tid >> 4] = hin[(bmA + (tid >> 4)) * Hq + k0 + (tid & 15)];
#pragma unroll
                for (int l = 0; l < 4; l++) {
                    int idx = tid + l * 256;
                    int c = idx >> 4, kk = idx & 15;
                    int h = c >> 2, g = c & 3;
                    Bs[kk][c] = Whh[(g * Hq + h0A + h) * Hq + k0 + kk];
                }
                __syncthreads();
#pragma unroll
                for (int kk = 0; kk < 16; kk++) {
                    float a = As[kk][tyA];
                    float4 b4 = *reinterpret_cast<const float4*>(&Bs[kk][txA * 4]);
                    acc[0] = fmaf(a, b4.x, acc[0]);
                    acc[1] = fmaf(a, b4.y, acc[1]);
                    acc[2] = fmaf(a, b4.z, acc[2]);
                    acc[3] = fmaf(a, b4.w, acc[3]);
                }
                __syncthreads();
            }
            int bb = bmA + tyA, h = h0A + txA;
            size_t xrow = ((size_t)d_chosen[bb] * Bq + bb) * G4;
            float gi = acc[0] + d_Dg[xrow + h]          + bih[h]          + bhh[h];
            float gf = acc[1] + d_Dg[xrow + Hq + h]     + bih[Hq + h]     + bhh[Hq + h];
            float gg = acc[2] + d_Dg[xrow + 2*Hq + h]   + bih[2*Hq + h]   + bhh[2*Hq + h];
            float go = acc[3] + d_Dg[xrow + 3*Hq + h]   + bih[3*Hq + h]   + bhh[3*Hq + h];
            int idx = bb * Hq + h;
            float cc = d_c[idx];
            float cn = xsigmoid(gf) * cc + xsigmoid(gi) * xtanh(gg);
            float hn = xsigmoid(go) * xtanh(cn);
            d_c[idx] = cn;
            hout[idx] = hn;
        }
        gsync<NB_DEC>(gen);

        // ---- Phase C: q + attention logits + gumbel argmax + log-softmax ----
        {
            int n = Sq - 1 - t;
            const float* gum = d_gum + ((size_t)t * Bq + b) * Sq;

            // q[b][tid] = sum_k h[b][k] * Wq[tid][k], ascending k (bit-identical to GEMM order)
            hs[tid] = hout[b * Hq + tid];
            ls[tid] = MASKVAL;
            ls[tid + 256] = MASKVAL;
            __syncthreads();
            float qv = 0.0f;
#pragma unroll 16
            for (int k = 0; k < Hq; k++)
                qv = fmaf(hs[k], __ldg(&d_WqT[k * Hq + tid]), qv);
            qs[tid] = qv;
            __syncthreads();

            const float4* qs4 = reinterpret_cast<const float4*>(qs);
            float4 q0 = qs4[lane], q1 = qs4[lane + 32];
            float4 v0 = vs4[lane], v1 = vs4[lane + 32];
            const int* lst = d_plist + b * Sq;
            const float* rbase = d_refproj + (size_t)b * Sq * Hq;

            for (int k0 = w * 4; k0 < n; k0 += 32) {
                int4 sxv = *reinterpret_cast<const int4*>(lst + k0);
                int sx[4] = {sxv.x, sxv.y, sxv.z, sxv.w};
                float4 ra[4], rb[4];
#pragma unroll
                for (int j = 0; j < 4; j++) {
                    const float4* p = reinterpret_cast<const float4*>(
                        rbase + (size_t)sx[j] * Hq);
                    ra[j] = p[lane];
                    rb[j] = p[lane + 32];
                }
                float sums[4];
#pragma unroll
                for (int j = 0; j < 4; j++) {
                    float s = 0.0f, t0, t1;
                    xtanh2(q0.x + ra[j].x, q0.y + ra[j].y, t0, t1);
                    s = fmaf(v0.x, t0, s);
                    s = fmaf(v0.y, t1, s);
                    xtanh2(q0.z + ra[j].z, q0.w + ra[j].w, t0, t1);
                    s = fmaf(v0.z, t0, s);
                    s = fmaf(v0.w, t1, s);
                    xtanh2(q1.x + rb[j].x, q1.y + rb[j].y, t0, t1);
                    s = fmaf(v1.x, t0, s);
                    s = fmaf(v1.y, t1, s);
                    xtanh2(q1.z + rb[j].z, q1.w + rb[j].w, t0, t1);
                    s = fmaf(v1.z, t0, s);
                    s = fmaf(v1.w, t1, s);
                    sums[j] = s;
                }
#pragma unroll
                for (int off = 16; off > 0; off >>= 1) {
                    sums[0] += __shfl_down_sync(0xffffffffu, sums[0], off);
                    sums[1] += __shfl_down_sync(0xffffffffu, sums[1], off);
                    sums[2] += __shfl_down_sync(0xffffffffu, sums[2], off);
                    sums[3] += __shfl_down_sync(0xffffffffu, sums[3], off);
                }
                if (lane == 0) {
#pragma unroll
                    for (int j = 0; j < 4; j++)
                        if (k0 + j < n) ls[sx[j]] = sums[j];
                }
            }
            __syncthreads();

            // candidate value = logit + gumbel (masked -> -inf)
            float l0 = ls[tid], l1 = ls[tid + 256];
            float o0 = (l0 == MASKVAL) ? -1e30f : l0 + gum[tid];
            float o1 = (l1 == MASKVAL) ? -1e30f : l1 + gum[tid + 256];

            // argmax via warp + cross-warp (exact total order: max value, tie -> min index)
            float bv; int bi;
            if (o0 >= o1) { bv = o0; bi = tid; }
            else { bv = o1; bi = tid + 256; }
#pragma unroll
            for (int off = 16; off > 0; off >>= 1) {
                float ov = __shfl_down_sync(0xffffffffu, bv, off);
                int oi = __shfl_down_sync(0xffffffffu, bi, off);
                if (ov > bv || (ov == bv && oi < bi)) { bv = ov; bi = oi; }
            }
            if (lane == 0) { rv[w] = bv; ri[w] = bi; }
            __syncthreads();
            if (w == 0) {
                float v8 = (lane < 8) ? rv[lane] : -1e38f;
                int i8 = (lane < 8) ? ri[lane] : 0x7fffffff;
#pragma unroll
                for (int off = 4; off > 0; off >>= 1) {
                    float ov = __shfl_down_sync(0xffffffffu, v8, off);
                    int oi = __shfl_down_sync(0xffffffffu, i8, off);
                    if (ov > v8 || (ov == v8 && oi < i8)) { v8 = ov; i8 = oi; }
                }
                if (lane == 0) s_ch = i8;
            }
            __syncthreads();
            int ch = s_ch;

            // max of logits
            float mx = fmaxf(l0, l1);
#pragma unroll
            for (int off = 16; off > 0; off >>= 1)
                mx = fmaxf(mx, __shfl_down_sync(0xffffffffu, mx, off));
            if (lane == 0) rv[w] = mx;
            __syncthreads();
            if (w == 0) {
                float m8 = (lane < 8) ? rv[lane] : -1e38f;
#pragma unroll
                for (int off = 4; off > 0; off >>= 1)
                    m8 = fmaxf(m8, __shfl_down_sync(0xffffffffu, m8, off));
                if (lane == 0) rv[0] = m8;
            }
            __syncthreads();
            float m = rv[0];

            // sum of exp
            float e = expf(l0 - m) + expf(l1 - m);
#pragma unroll
            for (int off = 16; off > 0; off >>= 1)
                e += __shfl_down_sync(0xffffffffu, e, off);
            if (lane == 0) sv[w] = e;
            __syncthreads();
            if (w == 0) {
                float s8 = (lane < 8) ? sv[lane] : 0.0f;
#pragma unroll
                for (int off = 4; off > 0; off >>= 1)
                    s8 += __shfl_down_sync(0xffffffffu, s8, off);
                if (lane == 0) {
                    float lp = (ls[ch] - m) - logf(s8);
                    d_lp[(size_t)t * Bq + b] = lp;
                    d_idx[(size_t)t * Bq + b] = ch;
                    d_chosen[b] = ch;
                    int base = b * Sq;
                    int kk = d_ppos[base + ch];
                    int sl = d_plist[base + n - 1];
                    d_plist[base + kk] = sl;
                    d_ppos[base + sl] = kk;
                    d_plist[base + n - 1] = ch;   // keep list a permutation (padded reads safe)
                }
            }
        }
        gsync<NB_DEC>(gen);
    }
}

// ---------------- init ----------------
__global__ __launch_bounds__(256) void k_init() {
    int i = blockIdx.x * 256 + threadIdx.x;
    if (i < 2 * Bq * Hq) d_hbuf[i] = 0.0f;
    if (i < Bq * Hq) d_c[i] = 0.0f;
    if (i < Bq * Sq) {
        int bb = i >> 9, s = i & (Sq - 1);
        if (s > 0) {
            d_plist[bb * Sq + (s - 1)] = s;
            d_ppos[bb * Sq + s] = s - 1;
        } else {
            d_plist[bb * Sq + (Sq - 1)] = 0;  // slot 511 unused; keep defined
            d_ppos[bb * Sq] = -1;
        }
    }
    if (i < Bq) d_chosen[i] = 0;
    if (i < (Sq - 1)) {
        unsigned int o0, o1;
        threefry2x32(0u, 1u, 0u, (unsigned int)i, o0, o1);
        d_keys[2 * i] = o0;
        d_keys[2 * i + 1] = o1;
    }
}

__global__ __launch_bounds__(256) void k_trans(const float* __restrict__ Wq) {
    int i = blockIdx.x * 256 + threadIdx.x;   // 65536
    int k = i >> 8, h = i & 255;
    d_WqT[k * Hq + h] = Wq[h * Hq + k];
}

__global__ __launch_bounds__(256) void k_gum() {
    size_t g = (size_t)blockIdx.x * 256 + threadIdx.x;
    int t = (int)(g >> 17);
    if (t >= Sq - 1) return;
    unsigned int r = (unsigned int)(g & 131071u);
    unsigned int bits = tf_bits32(d_keys[2 * t], d_keys[2 * t + 1], r);
    d_gum[g] = gumbel_from_bits(bits);
}

__global__ __launch_bounds__(256) void k_embed(const float* __restrict__ inputs,
                                               const float* __restrict__ W_embed) {
    int i = blockIdx.x * 256 + threadIdx.x;
    int e = i & (Eq - 1);
    int b = (i >> 8) & (Bq - 1);
    int s = i >> 16;
    const float* inp = inputs + ((size_t)b * Sq + s) * 2;
    d_emb[i] = fmaf(inp[1], W_embed[Eq + e], inp[0] * W_embed[e]);
}

// ---------------- big tiled GEMM: C = A[M][K] * W[N][K]^T ; 128x128x16, 8x8 ----------------
__global__ __launch_bounds__(256) void k_gemm2(const float* __restrict__ A,
                                               const float* __restrict__ W,
                                               float* __restrict__ C,
                                               int M, int N, int K, int transOut) {
    __shared__ float As[16][136];
    __shared__ float Bs[16][136];
    int bm = blockIdx.y * 128, bn = blockIdx.x * 128;
    int tid = threadIdx.x;
    int tx = tid & 15, ty = tid >> 4;
    float acc[8][8];
#pragma unroll
    for (int i = 0; i < 8; i++)
#pragma unroll
        for (int j = 0; j < 8; j++) acc[i][j] = 0.0f;

    for (int k0 = 0; k0 < K; k0 += 16) {
#pragma unroll
        for (int l = 0; l < 2; l++) {
            int slot = tid + l * 256;
            int r = slot >> 2, c4 = slot & 3;
            float4 va = *reinterpret_cast<const float4*>(&A[(size_t)(bm + r) * K + k0 + c4 * 4]);
            As[c4 * 4 + 0][r] = va.x;
            As[c4 * 4 + 1][r] = va.y;
            As[c4 * 4 + 2][r] = va.z;
            As[c4 * 4 + 3][r] = va.w;
        }
#pragma unroll
        for (int l = 0; l < 2; l++) {
            int slot = tid + l * 256;
            int r = slot >> 2, c4 = slot & 3;
            float4 vb = *reinterpret_cast<const float4*>(&W[(size_t)(bn + r) * K + k0 + c4 * 4]);
            Bs[c4 * 4 + 0][r] = vb.x;
            Bs[c4 * 4 + 1][r] = vb.y;
            Bs[c4 * 4 + 2][r] = vb.z;
            Bs[c4 * 4 + 3][r] = vb.w;
        }
        __syncthreads();
#pragma unroll
        for (int kk = 0; kk < 16; kk++) {
            float4 a0 = *reinterpret_cast<const float4*>(&As[kk][ty * 8]);
            float4 a1 = *reinterpret_cast<const float4*>(&As[kk][ty * 8 + 4]);
            float4 b0 = *reinterpret_cast<const float4*>(&Bs[kk][tx * 8]);
            float4 b1 = *reinterpret_cast<const float4*>(&Bs[kk][tx * 8 + 4]);
            float a[8] = {a0.x, a0.y, a0.z, a0.w, a1.x, a1.y, a1.z, a1.w};
            float b[8] = {b0.x, b0.y, b0.z, b0.w, b1.x, b1.y, b1.z, b1.w};
#pragma unroll
            for (int i = 0; i < 8; i++)
#pragma unroll
                for (int j = 0; j < 8; j++)
                    acc[i][j] = fmaf(a[i], b[j], acc[i][j]);
        }
        __syncthreads();
    }
#pragma unroll
    for (int i = 0; i < 8; i++) {
        int m = bm + ty * 8 + i;
        size_t row = transOut ? ((size_t)(m & (Bq - 1)) * Sq + (m >> 8)) : (size_t)m;
        float4 o0 = make_float4(acc[i][0], acc[i][1], acc[i][2], acc[i][3]);
        float4 o1 = make_float4(acc[i][4], acc[i][5], acc[i][6], acc[i][7]);
        *reinterpret_cast<float4*>(&C[row * N + bn + tx * 8]) = o0;
        *reinterpret_cast<float4*>(&C[row * N + bn + tx * 8 + 4]) = o1;
    }
}

__global__ __launch_bounds__(256) void k_final(float* __restrict__ out) {
    int i = blockIdx.x * 256 + threadIdx.x;
    const int NLP = Bq * (Sq - 1);
    if (i < NLP) {
        int b = i / (Sq - 1), t = i % (Sq - 1);
        out[i] = d_lp[(size_t)t * Bq + b];
    } else if (i < NLP + Bq * Sq) {
        int j = i - NLP;
        int b = j >> 9, s = j & (Sq - 1);
        out[i] = (s == 0) ? 0.0f : (float)d_idx[(size_t)(s - 1) * Bq + b];
    }
}

// ---------------- host ----------------
extern "C" void kernel_launch(void* const* d_in, const int* in_sizes, int n_in,
                              void* d_out, int out_size) {
    const float* inputs   = (const float*)d_in[0];
    const float* W_embed  = (const float*)d_in[1];
    const float* enc_Wih  = (const float*)d_in[2];
    const float* enc_Whh  = (const float*)d_in[3];
    const float* enc_bih  = (const float*)d_in[4];
    const float* enc_bhh  = (const float*)d_in[5];
    const float* dec_Wih  = (const float*)d_in[6];
    const float* dec_Whh  = (const float*)d_in[7];
    const float* dec_bih  = (const float*)d_in[8];
    const float* dec_bhh  = (const float*)d_in[9];
    const float* Wq       = (const float*)d_in[10];
    const float* Wref     = (const float*)d_in[11];
    const float* v        = (const float*)d_in[12];

    float *p_emb, *p_Xg, *p_Dg, *p_enc, *p_rp;
    cudaGetSymbolAddress((void**)&p_emb, d_emb);
    cudaGetSymbolAddress((void**)&p_Xg, d_XgEnc);
    cudaGetSymbolAddress((void**)&p_Dg, d_Dg);
    cudaGetSymbolAddress((void**)&p_enc, d_encout);
    cudaGetSymbolAddress((void**)&p_rp, d_refproj);

    k_init<<<512, 256>>>();
    k_trans<<<256, 256>>>(Wq);

    {
        size_t total = (size_t)(Sq - 1) * Bq * Sq;
        k_gum<<<(unsigned int)((total + 255) / 256), 256>>>();
    }

    k_embed<<<(Sq * Bq * Eq) / 256, 256>>>(inputs, W_embed);

    const int Mbig = Sq * Bq;  // 131072
    {
        dim3 grid(G4 / 128, Mbig / 128);
        k_gemm2<<<grid, 256>>>(p_emb, enc_Wih, p_Xg, Mbig, G4, Eq, 0);
    }
    {
        dim3 grid(G4 / 128, Mbig / 128);
        k_gemm2<<<grid, 256>>>(p_emb, dec_Wih, p_Dg, Mbig, G4, Eq, 0);
    }

    k_encoder<<<NB_ENC, 256>>>(enc_Whh, enc_bih, enc_bhh);

    {
        dim3 grid(Hq / 128, Mbig / 128);
        k_gemm2<<<grid, 256>>>(p_enc, Wref, p_rp, Mbig, Hq, Hq, 1);
    }

    k_decoder<<<NB_DEC, 256>>>(dec_Whh, dec_bih, dec_bhh, v);

    k_final<<<(Bq * (Sq - 1) + Bq * Sq + 255) / 256, 256>>>((float*)d_out);
}

// round 9
// speedup vs baseline: 2.8946x; 1.0933x over previous
#include <cuda_runtime.h>
#include <cstdint>

#define Bq 256
#define Sq 512
#define Eq 256
#define Hq 256
#define G4 1024
#define NB_ENC 128
#define NW 128
#define NB_DEC 256
#define MASKVAL -100000.0f
#define TINYF 1.17549435e-38f
#define CLV 7.90531110763549805f

typedef unsigned long long ull;

// ---------------- device globals (static scratch) ----------------
__device__ float d_emb[(size_t)Sq * Bq * Eq];        // [s][b][e]
__device__ float d_XgEnc[(size_t)Sq * Bq * G4];      // [s][b][j]
__device__ float d_Dg[(size_t)Sq * Bq * G4];         // [s][b][j]
__device__ float d_encout[(size_t)Sq * Bq * Hq];     // [s][b][h]
__device__ float d_refproj[(size_t)Bq * Sq * Hq];    // [b][s][h]
__device__ float d_gum[(size_t)(Sq - 1) * Bq * Sq];  // [t][b][s]
__device__ float d_WqT[Hq * Hq];                     // [k][h]
__device__ float d_hbuf[2 * Bq * Hq];
__device__ float d_c[Bq * Hq];
__device__ int d_plist[Bq * Sq];
__device__ int d_ppos[Bq * Sq];
__device__ int d_chosen[Bq];
__device__ unsigned int d_keys[(Sq - 1) * 2];
__device__ float d_lp[(Sq - 1) * Bq];
__device__ int d_idx[(Sq - 1) * Bq];
__device__ int d_xgcnt[Sq];
__device__ unsigned int g_enc_done = 0;
__device__ unsigned int g_cnt = 0;
__device__ unsigned int g_gen = 0;

// ---------------- f32x2 packed helpers ----------------
__device__ __forceinline__ ull pk2(float lo, float hi) {
    ull r;
    asm("mov.b64 %0, {%1, %2};" : "=l"(r) : "f"(lo), "f"(hi));
    return r;
}
__device__ __forceinline__ void upk2(ull v, float& lo, float& hi) {
    asm("mov.b64 {%0, %1}, %2;" : "=f"(lo), "=f"(hi) : "l"(v));
}
__device__ __forceinline__ ull fma2(ull a, ull b, ull c) {
    ull d;
    asm("fma.rn.f32x2 %0, %1, %2, %3;" : "=l"(d) : "l"(a), "l"(b), "l"(c));
    return d;
}
__device__ __forceinline__ ull mul2(ull a, ull b) {
    ull d;
    asm("mul.rn.f32x2 %0, %1, %2;" : "=l"(d) : "l"(a), "l"(b));
    return d;
}
__device__ __forceinline__ ull pk1(float c) { return pk2(c, c); }

// ---------------- math helpers ----------------
// exact scalar tanh (XLA semantics) — used in LSTM cells (feedback path)
__device__ __forceinline__ float xtanh(float x) {
    float ax = fabsf(x);
    float xc = fminf(fmaxf(x, -CLV), CLV);
    float x2 = xc * xc;
    float p = -2.76076847742355e-16f;
    p = fmaf(p, x2, 2.00018790482477e-13f);
    p = fmaf(p, x2, -8.60467152213735e-11f);
    p = fmaf(p, x2, 5.12229709037114e-08f);
    p = fmaf(p, x2, 1.48572235717979e-05f);
    p = fmaf(p, x2, 6.37261928875436e-04f);
    p = fmaf(p, x2, 4.89352455891786e-03f);
    float q = 1.19825839466702e-06f;
    q = fmaf(q, x2, 1.18534705686654e-04f);
    q = fmaf(q, x2, 2.26843463243900e-03f);
    q = fmaf(q, x2, 4.89352518554385e-03f);
    float t = (xc * p) / q;
    return (ax < 0.0004f) ? x : t;
}

// packed tanh for logits: poly exact, reciprocal via rcp.approx + 1 NR (~1 ulp),
// no tiny-x select (1e-13-scale effect). X must be pre-clamped & packed.
__device__ __forceinline__ ull xtanh2pk(ull X) {
    ull x2 = mul2(X, X);
    ull p = pk1(-2.76076847742355e-16f);
    p = fma2(p, x2, pk1(2.00018790482477e-13f));
    p = fma2(p, x2, pk1(-8.60467152213735e-11f));
    p = fma2(p, x2, pk1(5.12229709037114e-08f));
    p = fma2(p, x2, pk1(1.48572235717979e-05f));
    p = fma2(p, x2, pk1(6.37261928875436e-04f));
    p = fma2(p, x2, pk1(4.89352455891786e-03f));
    ull q = pk1(1.19825839466702e-06f);
    q = fma2(q, x2, pk1(1.18534705686654e-04f));
    q = fma2(q, x2, pk1(2.26843463243900e-03f));
    q = fma2(q, x2, pk1(4.89352518554385e-03f));
    ull num = mul2(X, p);
    float qa, qb;
    upk2(q, qa, qb);
    float ra, rb;
    asm("rcp.approx.f32 %0, %1;" : "=f"(ra) : "f"(qa));
    asm("rcp.approx.f32 %0, %1;" : "=f"(rb) : "f"(qb));
    ull rr = pk2(ra, rb);
    ull nq = q ^ 0x8000000080000000ULL;
    ull e = fma2(nq, rr, pk1(1.0f));
    rr = fma2(e, rr, rr);
    return mul2(num, rr);
}

__device__ __forceinline__ ull clamp_pack(float a, float b) {
    float ca = fminf(fmaxf(a, -CLV), CLV);
    float cb = fminf(fmaxf(b, -CLV), CLV);
    return pk2(ca, cb);
}

__device__ __forceinline__ float xsigmoid(float x) {
    return 1.0f / (1.0f + expf(-x));
}

__device__ __forceinline__ unsigned int rotl32(unsigned int v, int r) {
    return (v << r) | (v >> (32 - r));
}

__device__ __forceinline__ void threefry2x32(unsigned int k0, unsigned int k1,
                                             unsigned int x0, unsigned int x1,
                                             unsigned int& o0, unsigned int& o1) {
    unsigned int ks2 = k0 ^ k1 ^ 0x1BD11BDAu;
    x0 += k0; x1 += k1;
#define TF_RND(r) { x0 += x1; x1 = rotl32(x1, r); x1 ^= x0; }
    TF_RND(13) TF_RND(15) TF_RND(26) TF_RND(6)
    x0 += k1; x1 += ks2 + 1u;
    TF_RND(17) TF_RND(29) TF_RND(16) TF_RND(24)
    x0 += ks2; x1 += k0 + 2u;
    TF_RND(13) TF_RND(15) TF_RND(26) TF_RND(6)
    x0 += k0; x1 += k1 + 3u;
    TF_RND(17) TF_RND(29) TF_RND(16) TF_RND(24)
    x0 += k1; x1 += ks2 + 4u;
    TF_RND(13) TF_RND(15) TF_RND(26) TF_RND(6)
    x0 += ks2; x1 += k0 + 5u;
#undef TF_RND
    o0 = x0; o1 = x1;
}

__device__ __forceinline__ unsigned int tf_bits32(unsigned int k0, unsigned int k1,
                                                  unsigned int idx) {
    unsigned int o0, o1;
    threefry2x32(k0, k1, 0u, idx, o0, o1);
    return o0 ^ o1;
}

__device__ __forceinline__ float gumbel_from_bits(unsigned int bits) {
    float f = __uint_as_float((bits >> 9) | 0x3f800000u) - 1.0f;
    float u = f + TINYF;
    u = fmaxf(TINYF, u);
    return -logf(-logf(u));
}

// ---------------- grid-wide barrier ----------------
template <int NBLK>
__device__ __forceinline__ void gsync(unsigned int& gen) {
    __syncthreads();
    if (threadIdx.x == 0) {
        __threadfence();
        unsigned int t = atomicAdd(&g_cnt, 1u);
        if (t == NBLK - 1) {
            atomicExch(&g_cnt, 0u);
            __threadfence();
            atomicExch(&g_gen, gen + 1);
        } else {
            volatile unsigned int* p = &g_gen;
            while ((int)(*p - (gen + 1)) < 0) { }
            __threadfence();
        }
    }
    gen++;
    __syncthreads();
}

// ---------------- worker GEMM tile: C[128 x 64] = A[M][K] @ W[N][K]^T ----------------
// ascending-k accumulation (bit-identical to previous k_gemm2 results)
__device__ void wtile(const float* __restrict__ A, const float* __restrict__ W,
                      float* __restrict__ C, int K, int N, int bm, int bn,
                      int transOut, int tid, float (*As)[132], float (*Bs)[68]) {
    int tx = tid & 15, ty = tid >> 4;
    float acc[8][4];
#pragma unroll
    for (int i = 0; i < 8; i++)
#pragma unroll
        for (int j = 0; j < 4; j++) acc[i][j] = 0.0f;

    for (int k0 = 0; k0 < K; k0 += 16) {
#pragma unroll
        for (int l = 0; l < 2; l++) {
            int slot = tid + l * 256;
            int r = slot >> 2, c4 = slot & 3;
            float4 va = *reinterpret_cast<const float4*>(&A[(size_t)(bm + r) * K + k0 + c4 * 4]);
            As[c4 * 4 + 0][r] = va.x;
            As[c4 * 4 + 1][r] = va.y;
            As[c4 * 4 + 2][r] = va.z;
            As[c4 * 4 + 3][r] = va.w;
        }
        {
            int r = tid >> 2, c4 = tid & 3;
            float4 vb = *reinterpret_cast<const float4*>(&W[(size_t)(bn + r) * K + k0 + c4 * 4]);
            Bs[c4 * 4 + 0][r] = vb.x;
            Bs[c4 * 4 + 1][r] = vb.y;
            Bs[c4 * 4 + 2][r] = vb.z;
            Bs[c4 * 4 + 3][r] = vb.w;
        }
        __syncthreads();
#pragma unroll
        for (int kk = 0; kk < 16; kk++) {
            float4 a0 = *reinterpret_cast<const float4*>(&As[kk][ty * 8]);
            float4 a1 = *reinterpret_cast<const float4*>(&As[kk][ty * 8 + 4]);
            float4 b0 = *reinterpret_cast<const float4*>(&Bs[kk][tx * 4]);
            float a[8] = {a0.x, a0.y, a0.z, a0.w, a1.x, a1.y, a1.z, a1.w};
            float b[4] = {b0.x, b0.y, b0.z, b0.w};
#pragma unroll
            for (int i = 0; i < 8; i++)
#pragma unroll
                for (int j = 0; j < 4; j++)
                    acc[i][j] = fmaf(a[i], b[j], acc[i][j]);
        }
        __syncthreads();
    }
#pragma unroll
    for (int i = 0; i < 8; i++) {
        int m = bm + ty * 8 + i;
        size_t row = transOut ? ((size_t)(m & (Bq - 1)) * Sq + (m >> 8)) : (size_t)m;
        *reinterpret_cast<float4*>(&C[row * N + bn + tx * 4]) =
            make_float4(acc[i][0], acc[i][1], acc[i][2], acc[i][3]);
    }
}

// ---------------- encoder lstm phase (128 blocks, 32b x 16h tiles) ----------------
__device__ __forceinline__ void lstm_phase_enc(
    int bid, int tid,
    const float* __restrict__ hin, float* __restrict__ hout,
    const float* __restrict__ Whh, const float* __restrict__ bih,
    const float* __restrict__ bhh,
    const float* __restrict__ xg,
    float* __restrict__ encout,
    float (*As)[34], float (*Bs)[68])
{
    int tb = bid >> 4, th = bid & 15;
    int bm = tb * 32, h0 = th * 16;
    int tx = tid & 15, ty = tid >> 4;
    float acc[2][4];
#pragma unroll
    for (int i = 0; i < 2; i++)
#pragma unroll
        for (int g = 0; g < 4; g++) acc[i][g] = 0.0f;

    for (int k0 = 0; k0 < Hq; k0 += 16) {
#pragma unroll
        for (int l = 0; l < 2; l++) {
            int idx = tid + l * 256;
            int m = idx >> 4, kk = idx & 15;
            As[kk][m] = hin[(bm + m) * Hq + k0 + kk];
        }
#pragma unroll
        for (int l = 0; l < 4; l++) {
            int idx = tid + l * 256;
            int c = idx >> 4, kk = idx & 15;
            int h = c >> 2, g = c & 3;
            Bs[kk][c] = Whh[(g * Hq + h0 + h) * Hq + k0 + kk];
        }
        __syncthreads();
#pragma unroll
        for (int kk = 0; kk < 16; kk++) {
            float2 a2 = *reinterpret_cast<const float2*>(&As[kk][ty * 2]);
            float4 b4 = *reinterpret_cast<const float4*>(&Bs[kk][tx * 4]);
            acc[0][0] = fmaf(a2.x, b4.x, acc[0][0]);
            acc[0][1] = fmaf(a2.x, b4.y, acc[0][1]);
            acc[0][2] = fmaf(a2.x, b4.z, acc[0][2]);
            acc[0][3] = fmaf(a2.x, b4.w, acc[0][3]);
            acc[1][0] = fmaf(a2.y, b4.x, acc[1][0]);
            acc[1][1] = fmaf(a2.y, b4.y, acc[1][1]);
            acc[1][2] = fmaf(a2.y, b4.z, acc[1][2]);
            acc[1][3] = fmaf(a2.y, b4.w, acc[1][3]);
        }
        __syncthreads();
    }

    int h = h0 + tx;
#pragma unroll
    for (int i = 0; i < 2; i++) {
        int b = bm + ty * 2 + i;
        size_t xrow = (size_t)b * G4;
        float gi = acc[i][0] + xg[xrow + h]          + bih[h]          + bhh[h];
        float gf = acc[i][1] + xg[xrow + Hq + h]     + bih[Hq + h]     + bhh[Hq + h];
        float gg = acc[i][2] + xg[xrow + 2*Hq + h]   + bih[2*Hq + h]   + bhh[2*Hq + h];
        float go = acc[i][3] + xg[xrow + 3*Hq + h]   + bih[3*Hq + h]   + bhh[3*Hq + h];
        int idx = b * Hq + h;
        float cc = d_c[idx];
        float cn = xsigmoid(gf) * cc + xsigmoid(gi) * xtanh(gg);
        float hn = xsigmoid(go) * xtanh(cn);
        d_c[idx] = cn;
        hout[idx] = hn;
        encout[idx] = hn;
    }
}

// ---------------- fused encoder + precompute workers (256 blocks, 2 CTA/SM) ----------------
__global__ __launch_bounds__(256, 2) void k_encfuse(const float* __restrict__ Whh,
                                                    const float* __restrict__ bih,
                                                    const float* __restrict__ bhh,
                                                    const float* __restrict__ Wih_enc,
                                                    const float* __restrict__ Wih_dec,
                                                    const float* __restrict__ Wref) {
    __shared__ float EA[16][34];
    __shared__ float SA[16][132];
    __shared__ float SB[16][68];
    __shared__ unsigned int s_gen0;
    int tid = threadIdx.x, bid = blockIdx.x;

    if (bid < NB_ENC) {
        // -------- encoder blocks --------
        if (tid == 0) s_gen0 = atomicAdd(&g_gen, 0u);
        __syncthreads();
        unsigned int gen = s_gen0;
        for (int s = 0; s < Sq; s++) {
            if (tid == 0) {
                volatile int* c = d_xgcnt;
                while (c[s] < 32) { }
            }
            __syncthreads();
            const float* hin = d_hbuf + (s & 1) * (Bq * Hq);
            float* hout = d_hbuf + ((s & 1) ^ 1) * (Bq * Hq);
            lstm_phase_enc(bid, tid, hin, hout, Whh, bih, bhh,
                           d_XgEnc + (size_t)s * Bq * G4,
                           d_encout + (size_t)s * Bq * Hq, EA, SB);
            gsync<NB_ENC>(gen);
            if (bid == 0 && tid == 0) atomicExch(&g_enc_done, (unsigned int)(s + 1));
        }
    } else {
        // -------- worker blocks --------
        int wd = bid - NB_ENC;
        // 1) Xg tiles, s-ascending, publish per-s completion (32 tiles per s)
        for (int j = wd; j < 16384; j += NW) {
            int bmT = j >> 4, bnT = j & 15;
            wtile(d_emb, Wih_enc, d_XgEnc, Eq, G4, bmT * 128, bnT * 64, 0, tid, SA, SB);
            __syncthreads();
            if (tid == 0) { __threadfence(); atomicAdd(&d_xgcnt[bmT >> 1], 1); }
        }
        // 2) Dg tiles
        for (int j = wd; j < 16384; j += NW) {
            int bmT = j >> 4, bnT = j & 15;
            wtile(d_emb, Wih_dec, d_Dg, Eq, G4, bmT * 128, bnT * 64, 0, tid, SA, SB);
            __syncthreads();
        }
        // 3) gumbel noise
        {
            size_t total = (size_t)(Sq - 1) * Bq * Sq;
            for (size_t g = (size_t)(wd * 256 + tid); g < total; g += (size_t)NW * 256) {
                int t = (int)(g >> 17);
                unsigned int r = (unsigned int)(g & 131071u);
                d_gum[g] = gumbel_from_bits(tf_bits32(d_keys[2 * t], d_keys[2 * t + 1], r));
            }
        }
        // 4) refproj tiles (gated on encoder progress; usually no wait)
        for (int j = wd; j < 4096; j += NW) {
            int bmT = j >> 2, bnT = j & 3;
            unsigned int sneed = (unsigned int)((bmT * 128 + 127) >> 8) + 1u;
            if (tid == 0) {
                volatile unsigned int* p = &g_enc_done;
                while (*p < sneed) { }
            }
            __syncthreads();
            wtile(d_encout, Wref, d_refproj, Hq, Hq, bmT * 128, bnT * 64, 1, tid, SA, SB);
            __syncthreads();
        }
    }
}

// ---------------- persistent decoder: 256 blocks, 2 CTA/SM, 2 phases/step ----------------
__global__ __launch_bounds__(256, 2) void k_decoder(const float* __restrict__ Whh,
                                                    const float* __restrict__ bih,
                                                    const float* __restrict__ bhh,
                                                    const float* __restrict__ vvec) {
    __shared__ float As[16][17];
    __shared__ float Bs[16][68];
    __shared__ __align__(16) float hs[Hq];
    __shared__ __align__(16) float qs[Hq];
    __shared__ __align__(16) float vsm[Hq];
    __shared__ __align__(16) float ls[Sq];
    __shared__ float rv[8];
    __shared__ int   ri[8];
    __shared__ float sv[8];
    __shared__ int   s_ch;
    __shared__ unsigned int s_gen0;

    int tid = threadIdx.x, bid = blockIdx.x;
    if (tid == 0) s_gen0 = atomicAdd(&g_gen, 0u);
    vsm[tid] = vvec[tid];
    __syncthreads();
    unsigned int gen = s_gen0;

    int tbA = bid >> 4, thA = bid & 15;
    int bmA = tbA * 16, h0A = thA * 16;
    int txA = tid & 15, tyA = tid >> 4;
    int w = tid >> 5, lane = tid & 31;
    int b = bid;

    const float4* vs4 = reinterpret_cast<const float4*>(vsm);
    float4 v0 = vs4[lane], v1 = vs4[lane + 32];
    ull vp0 = pk2(v0.x, v0.y), vp1 = pk2(v0.z, v0.w);
    ull vp2 = pk2(v1.x, v1.y), vp3 = pk2(v1.z, v1.w);

    for (int t = 0; t < Sq - 1; t++) {
        const float* hin = d_hbuf + (t & 1) * (Bq * Hq);
        float* hout = d_hbuf + ((t & 1) ^ 1) * (Bq * Hq);

        // ---- Phase A: gates GEMM + LSTM cell (all 256 blocks; 16b x 16h tiles) ----
        {
            float acc[4] = {0.0f, 0.0f, 0.0f, 0.0f};
            for (int k0 = 0; k0 < Hq; k0 += 16) {
                As[tid & 15][tid >> 4] = hin[(bmA + (tid >> 4)) * Hq + k0 + (tid & 15)];
#pragma unroll
                for (int l = 0; l < 4; l++) {
                    int idx = tid + l * 256;
                    int c = idx >> 4, kk = idx & 15;
                    int h = c >> 2, g = c & 3;
                    Bs[kk][c] = Whh[(g * Hq + h0A + h) * Hq + k0 + kk];
                }
                __syncthreads();
#pragma unroll
                for (int kk = 0; kk < 16; kk++) {
                    float a = As[kk][tyA];
                    float4 b4 = *reinterpret_cast<const float4*>(&Bs[kk][txA * 4]);
                    acc[0] = fmaf(a, b4.x, acc[0]);
                    acc[1] = fmaf(a, b4.y, acc[1]);
                    acc[2] = fmaf(a, b4.z, acc[2]);
                    acc[3] = fmaf(a, b4.w, acc[3]);
                }
                __syncthreads();
            }
            int bb = bmA + tyA, h = h0A + txA;
            size_t xrow = ((size_t)d_chosen[bb] * Bq + bb) * G4;
            float gi = acc[0] + d_Dg[xrow + h]          + bih[h]          + bhh[h];
            float gf = acc[1] + d_Dg[xrow + Hq + h]     + bih[Hq + h]     + bhh[Hq + h];
            float gg = acc[2] + d_Dg[xrow + 2*Hq + h]   + bih[2*Hq + h]   + bhh[2*Hq + h];
            float go = acc[3] + d_Dg[xrow + 3*Hq + h]   + bih[3*Hq + h]   + bhh[3*Hq + h];
            int idx = bb * Hq + h;
            float cc = d_c[idx];
            float cn = xsigmoid(gf) * cc + xsigmoid(gi) * xtanh(gg);
            float hn = xsigmoid(go) * xtanh(cn);
            d_c[idx] = cn;
            hout[idx] = hn;
        }
        gsync<NB_DEC>(gen);

        // ---- Phase C: q + attention logits + gumbel argmax + log-softmax ----
        {
            int n = Sq - 1 - t;
            const float* gum = d_gum + ((size_t)t * Bq + b) * Sq;

            hs[tid] = hout[b * Hq + tid];
            ls[tid] = MASKVAL;
            ls[tid + 256] = MASKVAL;
            __syncthreads();
            float qv = 0.0f;
#pragma unroll 16
            for (int k = 0; k < Hq; k++)
                qv = fmaf(hs[k], __ldg(&d_WqT[k * Hq + tid]), qv);
            qs[tid] = qv;
            __syncthreads();

            const float4* qs4 = reinterpret_cast<const float4*>(qs);
            float4 q0 = qs4[lane], q1 = qs4[lane + 32];
            const int* lst = d_plist + b * Sq;
            const float* rbase = d_refproj + (size_t)b * Sq * Hq;

            for (int k0 = w * 4; k0 < n; k0 += 32) {
                int4 sxv = *reinterpret_cast<const int4*>(lst + k0);
                int sx[4] = {sxv.x, sxv.y, sxv.z, sxv.w};
                float4 ra[4], rb[4];
#pragma unroll
                for (int j = 0; j < 4; j++) {
                    const float4* p = reinterpret_cast<const float4*>(
                        rbase + (size_t)sx[j] * Hq);
                    ra[j] = p[lane];
                    rb[j] = p[lane + 32];
                }
                float sums[4];
#pragma unroll
                for (int j = 0; j < 4; j++) {
                    ull s2 = 0ULL;
                    ull T;
                    T = xtanh2pk(clamp_pack(q0.x + ra[j].x, q0.y + ra[j].y));
                    s2 = fma2(vp0, T, s2);
                    T = xtanh2pk(clamp_pack(q0.z + ra[j].z, q0.w + ra[j].w));
                    s2 = fma2(vp1, T, s2);
                    T = xtanh2pk(clamp_pack(q1.x + rb[j].x, q1.y + rb[j].y));
                    s2 = fma2(vp2, T, s2);
                    T = xtanh2pk(clamp_pack(q1.z + rb[j].z, q1.w + rb[j].w));
                    s2 = fma2(vp3, T, s2);
                    float lo, hi;
                    upk2(s2, lo, hi);
                    sums[j] = lo + hi;
                }
#pragma unroll
                for (int off = 16; off > 0; off >>= 1) {
                    sums[0] += __shfl_down_sync(0xffffffffu, sums[0], off);
                    sums[1] += __shfl_down_sync(0xffffffffu, sums[1], off);
                    sums[2] += __shfl_down_sync(0xffffffffu, sums[2], off);
                    sums[3] += __shfl_down_sync(0xffffffffu, sums[3], off);
                }
                if (lane == 0) {
#pragma unroll
                    for (int j = 0; j < 4; j++)
                        if (k0 + j < n) ls[sx[j]] = sums[j];
                }
            }
            __syncthreads();

            float l0 = ls[tid], l1 = ls[tid + 256];
            float o0 = (l0 == MASKVAL) ? -1e30f : l0 + gum[tid];
            float o1 = (l1 == MASKVAL) ? -1e30f : l1 + gum[tid + 256];

            // argmax (max value, tie -> min index)
            float bv; int bi;
            if (o0 >= o1) { bv = o0; bi = tid; }
            else { bv = o1; bi = tid + 256; }
#pragma unroll
            for (int off = 16; off > 0; off >>= 1) {
                float ov = __shfl_down_sync(0xffffffffu, bv, off);
                int oi = __shfl_down_sync(0xffffffffu, bi, off);
                if (ov > bv || (ov == bv && oi < bi)) { bv = ov; bi = oi; }
            }
            if (lane == 0) { rv[w] = bv; ri[w] = bi; }
            __syncthreads();
            if (w == 0) {
                float v8 = (lane < 8) ? rv[lane] : -1e38f;
                int i8 = (lane < 8) ? ri[lane] : 0x7fffffff;
#pragma unroll
                for (int off = 4; off > 0; off >>= 1) {
                    float ov = __shfl_down_sync(0xffffffffu, v8, off);
                    int oi = __shfl_down_sync(0xffffffffu, i8, off);
                    if (ov > v8 || (ov == v8 && oi < i8)) { v8 = ov; i8 = oi; }
                }
                if (lane == 0) s_ch = i8;
            }
            __syncthreads();
            int ch = s_ch;

            // max of logits
            float mx = fmaxf(l0, l1);
#pragma unroll
            for (int off = 16; off > 0; off >>= 1)
                mx = fmaxf(mx, __shfl_down_sync(0xffffffffu, mx, off));
            if (lane == 0) rv[w] = mx;
            __syncthreads();
            if (w == 0) {
                float m8 = (lane < 8) ? rv[lane] : -1e38f;
#pragma unroll
                for (int off = 4; off > 0; off >>= 1)
                    m8 = fmaxf(m8, __shfl_down_sync(0xffffffffu, m8, off));
                if (lane == 0) rv[0] = m8;
            }
            __syncthreads();
            float m = rv[0];

            // sum of exp
            float e = expf(l0 - m) + expf(l1 - m);
#pragma unroll
            for (int off = 16; off > 0; off >>= 1)
                e += __shfl_down_sync(0xffffffffu, e, off);
            if (lane == 0) sv[w] = e;
            __syncthreads();
            if (w == 0) {
                float s8 = (lane < 8) ? sv[lane] : 0.0f;
#pragma unroll
                for (int off = 4; off > 0; off >>= 1)
                    s8 += __shfl_down_sync(0xffffffffu, s8, off);
                if (lane == 0) {
                    float lp = (ls[ch] - m) - logf(s8);
                    d_lp[(size_t)t * Bq + b] = lp;
                    d_idx[(size_t)t * Bq + b] = ch;
                    d_chosen[b] = ch;
                    int base = b * Sq;
                    int kk = d_ppos[base + ch];
                    int sl = d_plist[base + n - 1];
                    d_plist[base + kk] = sl;
                    d_ppos[base + sl] = kk;
                    d_plist[base + n - 1] = ch;
                }
            }
        }
        gsync<NB_DEC>(gen);
    }
}

// ---------------- init ----------------
__global__ __launch_bounds__(256) void k_init() {
    int i = blockIdx.x * 256 + threadIdx.x;
    if (i < 2 * Bq * Hq) d_hbuf[i] = 0.0f;
    if (i < Bq * Hq) d_c[i] = 0.0f;
    if (i < Bq * Sq) {
        int bb = i >> 9, s = i & (Sq - 1);
        if (s > 0) {
            d_plist[bb * Sq + (s - 1)] = s;
            d_ppos[bb * Sq + s] = s - 1;
        } else {
            d_plist[bb * Sq + (Sq - 1)] = 0;
            d_ppos[bb * Sq] = -1;
        }
    }
    if (i < Bq) d_chosen[i] = 0;
    if (i < Sq) d_xgcnt[i] = 0;
    if (i == 0) g_enc_done = 0u;
    if (i < (Sq - 1)) {
        unsigned int o0, o1;
        threefry2x32(0u, 1u, 0u, (unsigned int)i, o0, o1);
        d_keys[2 * i] = o0;
        d_keys[2 * i + 1] = o1;
    }
}

__global__ __launch_bounds__(256) void k_trans(const float* __restrict__ Wq) {
    int i = blockIdx.x * 256 + threadIdx.x;
    int k = i >> 8, h = i & 255;
    d_WqT[k * Hq + h] = Wq[h * Hq + k];
}

__global__ __launch_bounds__(256) void k_embed(const float* __restrict__ inputs,
                                               const float* __restrict__ W_embed) {
    int i = blockIdx.x * 256 + threadIdx.x;
    int e = i & (Eq - 1);
    int b = (i >> 8) & (Bq - 1);
    int s = i >> 16;
    const float* inp = inputs + ((size_t)b * Sq + s) * 2;
    d_emb[i] = fmaf(inp[1], W_embed[Eq + e], inp[0] * W_embed[e]);
}

__global__ __launch_bounds__(256) void k_final(float* __restrict__ out) {
    int i = blockIdx.x * 256 + threadIdx.x;
    const int NLP = Bq * (Sq - 1);
    if (i < NLP) {
        int b = i / (Sq - 1), t = i % (Sq - 1);
        out[i] = d_lp[(size_t)t * Bq + b];
    } else if (i < NLP + Bq * Sq) {
        int j = i - NLP;
        int b = j >> 9, s = j & (Sq - 1);
        out[i] = (s == 0) ? 0.0f : (float)d_idx[(size_t)(s - 1) * Bq + b];
    }
}

// ---------------- host ----------------
extern "C" void kernel_launch(void* const* d_in, const int* in_sizes, int n_in,
                              void* d_out, int out_size) {
    const float* inputs   = (const float*)d_in[0];
    const float* W_embed  = (const float*)d_in[1];
    const float* enc_Wih  = (const float*)d_in[2];
    const float* enc_Whh  = (const float*)d_in[3];
    const float* enc_bih  = (const float*)d_in[4];
    const float* enc_bhh  = (const float*)d_in[5];
    const float* dec_Wih  = (const float*)d_in[6];
    const float* dec_Whh  = (const float*)d_in[7];
    const float* dec_bih  = (const float*)d_in[8];
    const float* dec_bhh  = (const float*)d_in[9];
    const float* Wq       = (const float*)d_in[10];
    const float* Wref     = (const float*)d_in[11];
    const float* v        = (const float*)d_in[12];

    k_init<<<512, 256>>>();
    k_trans<<<256, 256>>>(Wq);
    k_embed<<<(Sq * Bq * Eq) / 256, 256>>>(inputs, W_embed);

    // fused: encoder (blocks 0-127) + precompute workers (blocks 128-255)
    k_encfuse<<<NB_ENC + NW, 256>>>(enc_Whh, enc_bih, enc_bhh,
                                    enc_Wih, dec_Wih, Wref);

    k_decoder<<<NB_DEC, 256>>>(dec_Whh, dec_bih, dec_bhh, v);

    k_final<<<(Bq * (Sq - 1) + Bq * Sq + 255) / 256, 256>>>((float*)d_out);
}